// round 7
// baseline (speedup 1.0000x reference)
#include <cuda_runtime.h>
#include <cuda_bf16.h>
#include <cstdint>

typedef unsigned int u32;
typedef unsigned long long u64t;

// ============================================================================
// g_prep: packed, fragment-ordered, bank-swizzled hi/lo bf16 split of W1.
// [kc 0..23][br 0..1][n 0..95][ks^(n&1)][q] -> 16B {bh0,bh1,bl0,bl1}
// ============================================================================
__device__ __align__(16) u32 g_prep[24 * 2 * 96 * 32];   // 589824 B

__device__ __forceinline__ u32 pack_bf16(float a, float b) {
    __nv_bfloat162 h = __floats2bfloat162_rn(a, b);
    return *(u32*)&h;
}

__global__ void prep_w1(const float* __restrict__ eW1, const float* __restrict__ sW1)
{
    int idx = blockIdx.x * 256 + threadIdx.x;        // 0 .. 36863
    if (idx >= 36864) return;
    int q  = idx & 3;
    int ks = (idx >> 2) & 1;
    int n  = (idx >> 3) % 96;
    int t  = (idx >> 3) / 96;
    int kc = t % 24;
    int br = t / 24;
    const float* W = (br ? sW1 : eW1) + (size_t)n * 768 + kc * 32 + ks * 16;
    float x0 = W[2*q], x1 = W[2*q+1], x2 = W[8+2*q], x3 = W[8+2*q+1];
    float h0 = __bfloat162float(__float2bfloat16(x0));
    float h1 = __bfloat162float(__float2bfloat16(x1));
    float h2 = __bfloat162float(__float2bfloat16(x2));
    float h3 = __bfloat162float(__float2bfloat16(x3));
    uint4 v;
    v.x = pack_bf16(x0, x1);
    v.y = pack_bf16(x2, x3);
    v.z = pack_bf16(x0 - h0, x1 - h1);
    v.w = pack_bf16(x2 - h2, x3 - h3);
    u32 off = (u32)kc * 24576 + (u32)br * 12288 + (u32)n * 128
            + (u32)((ks ^ (n & 1)) << 6) + (u32)q * 16;
    *(uint4*)((char*)g_prep + off) = v;
}

// ============================================================================
// helpers
// ============================================================================
__device__ __forceinline__ u32 smem_u32(const void* p) {
    u32 a;
    asm("{ .reg .u64 t; cvta.to.shared.u64 t, %1; cvt.u32.u64 %0, t; }" : "=r"(a) : "l"(p));
    return a;
}
__device__ __forceinline__ u64t fma2(u64t a, u64t b, u64t c) {
    u64t d;
    asm("fma.rn.f32x2 %0, %1, %2, %3;" : "=l"(d) : "l"(a), "l"(b), "l"(c));
    return d;
}
__device__ __forceinline__ float red2(u64t v) {
    return __uint_as_float((u32)v) + __uint_as_float((u32)(v >> 32));
}
__device__ __forceinline__ u64t pack2(float lo, float hi) {
    return (u64t)__float_as_uint(lo) | ((u64t)__float_as_uint(hi) << 32);
}
__device__ __forceinline__ void split4(float4 q, u64t& hv, u64t& lv) {
    __nv_bfloat162 h01 = __floats2bfloat162_rn(q.x, q.y);
    __nv_bfloat162 h23 = __floats2bfloat162_rn(q.z, q.w);
    float2 f01 = __bfloat1622float2(h01);
    float2 f23 = __bfloat1622float2(h23);
    __nv_bfloat162 l01 = __floats2bfloat162_rn(q.x - f01.x, q.y - f01.y);
    __nv_bfloat162 l23 = __floats2bfloat162_rn(q.z - f23.x, q.w - f23.y);
    hv = (u64t)(*(u32*)&h01) | ((u64t)(*(u32*)&h23) << 32);
    lv = (u64t)(*(u32*)&l01) | ((u64t)(*(u32*)&l23) << 32);
}
__device__ __forceinline__ void mma_bf16(float c[4], u32 a0, u32 a1, u32 a2, u32 a3,
                                         u32 b0, u32 b1) {
    asm volatile("mma.sync.aligned.m16n8k16.row.col.f32.bf16.bf16.f32 "
        "{%0,%1,%2,%3}, {%4,%5,%6,%7}, {%8,%9}, {%0,%1,%2,%3};"
        : "+f"(c[0]), "+f"(c[1]), "+f"(c[2]), "+f"(c[3])
        : "r"(a0), "r"(a1), "r"(a2), "r"(a3), "r"(b0), "r"(b1));
}

// ============================================================================
// smem layout (bytes)
//   A stages: stage*40960, hi at +0 (256 rows * 80B), lo at +20480
//   B stages: 81920 + stage*24576
//   weights:  131072 (12516 floats)
//   tail y1 overlays [0, 102400): 256 rows * 100 f
// ============================================================================
#define SM_B0   81920
#define B_STAGE 24576
#define SM_W    131072
#define SMEM_BYTES 181248
// weight region float offsets
#define OW2E 0
#define OW2S 4608
#define OW3E 9216
#define OW3S 10368
#define OW4E 11520
#define OW4S 11808
#define OW5  12096
#define OE5  12120
#define OSE  12132
#define OT0  12260
#define OT1  12388

__global__ __launch_bounds__(512, 1) void fused_mma(
    const float* __restrict__ in,
    const float* __restrict__ sW2, const float* __restrict__ sW3,
    const float* __restrict__ sW4, const float* __restrict__ sW5,
    const float* __restrict__ eW2, const float* __restrict__ eW3,
    const float* __restrict__ eW4, const float* __restrict__ eW5,
    const float* __restrict__ s_seq, const float* __restrict__ s_pair,
    const float* __restrict__ e_seq, const float* __restrict__ e_pair,
    const float* __restrict__ cross_w,
    float* __restrict__ out)
{
    extern __shared__ __align__(1024) char sm[];
    float* wf  = (float*)(sm + SM_W);
    float* y1f = (float*)sm;

    const int tid = threadIdx.x;
    const int r0g = blockIdx.x * 64;
    const bool is_cons = (tid < 256);
    const int ptid = tid & 255;               // producer index for tid>=256

    const float ep0 = e_pair[0], ep1 = e_pair[1];
    const float sp0 = s_pair[0], sp1 = s_pair[1];
    const float es0 = e_seq[0], es1 = e_seq[1], es2 = e_seq[2], es3 = e_seq[3];
    const float ss0 = s_seq[0], ss1 = s_seq[1], ss2 = s_seq[2], ss3 = s_seq[3];

    // ---- producer mapping ----
    const int rb = ptid >> 3;          // unit0 row 0..31 ; unit1 = rb+32
    const int sk = ptid & 7;
    const float* inp0 = in + (size_t)(r0g + rb) * 3072 + sk * 4;
    const float* inp1 = inp0 + (size_t)32 * 3072;

    // ---- consumer (mma) mapping: warp = m32 x n96 ----
    const int lane = tid & 31;
    const int w    = tid >> 5;         // consumers: 0..7
    const int br   = (w >> 2) & 1;     // 0=e, 1=s
    const int wm   = w & 3;
    const int fr   = lane >> 2;
    const int ql   = lane & 3;
    const int mb0  = br * 8 + wm * 2;

    u64t gprep;
    asm("cvta.to.global.u64 %0, %1;" : "=l"(gprep) : "l"((const void*)g_prep));
    const u32 b_sm = smem_u32(sm + SM_B0);

    float acc[2][12][4];
#pragma unroll
    for (int im = 0; im < 2; im++)
#pragma unroll
        for (int nf = 0; nf < 12; nf++)
#pragma unroll
            for (int c = 0; c < 4; c++) acc[im][nf][c] = 0.f;

    float4 sA0, sA1, sA2, sA3, sB0, sB1, sB2, sB3;

#define LOAD_STAGE(kcv) { \
    const float* p0 = inp0 + (kcv) * 32; \
    sA0 = *(const float4*)p0; sA1 = *(const float4*)(p0 + 768); \
    sA2 = *(const float4*)(p0 + 1536); sA3 = *(const float4*)(p0 + 2304); \
    const float* p1 = inp1 + (kcv) * 32; \
    sB0 = *(const float4*)p1; sB1 = *(const float4*)(p1 + 768); \
    sB2 = *(const float4*)(p1 + 1536); sB3 = *(const float4*)(p1 + 2304); }

#define BUILD_ONE(stage, roff, t0, t1, t2, t3) { \
    u32 off = (u32)(stage) * 40960 + (roff) * 160 + sk * 8; \
    float4 q; u64t hv, lv; \
    q.x = fmaxf(ep0*t0.x + ep1*t2.x, 0.f); q.y = fmaxf(ep0*t0.y + ep1*t2.y, 0.f); \
    q.z = fmaxf(ep0*t0.z + ep1*t2.z, 0.f); q.w = fmaxf(ep0*t0.w + ep1*t2.w, 0.f); \
    split4(q, hv, lv); \
    *(u64t*)(sm + off) = hv; *(u64t*)(sm + off + 20480) = lv; \
    q.x = fmaxf(es0*t0.x + es1*t1.x + es2*t2.x + es3*t3.x, 0.f); \
    q.y = fmaxf(es0*t0.y + es1*t1.y + es2*t2.y + es3*t3.y, 0.f); \
    q.z = fmaxf(es0*t0.z + es1*t1.z + es2*t2.z + es3*t3.z, 0.f); \
    q.w = fmaxf(es0*t0.w + es1*t1.w + es2*t2.w + es3*t3.w, 0.f); \
    split4(q, hv, lv); \
    *(u64t*)(sm + off + 80) = hv; *(u64t*)(sm + off + 80 + 20480) = lv; \
    q.x = fmaxf(sp0*t0.x + sp1*t2.x, 0.f); q.y = fmaxf(sp0*t0.y + sp1*t2.y, 0.f); \
    q.z = fmaxf(sp0*t0.z + sp1*t2.z, 0.f); q.w = fmaxf(sp0*t0.w + sp1*t2.w, 0.f); \
    split4(q, hv, lv); \
    *(u64t*)(sm + off + 10240) = hv; *(u64t*)(sm + off + 10240 + 20480) = lv; \
    q.x = fmaxf(ss0*t0.x + ss1*t1.x + ss2*t2.x + ss3*t3.x, 0.f); \
    q.y = fmaxf(ss0*t0.y + ss1*t1.y + ss2*t2.y + ss3*t3.y, 0.f); \
    q.z = fmaxf(ss0*t0.z + ss1*t1.z + ss2*t2.z + ss3*t3.z, 0.f); \
    q.w = fmaxf(ss0*t0.w + ss1*t1.w + ss2*t2.w + ss3*t3.w, 0.f); \
    split4(q, hv, lv); \
    *(u64t*)(sm + off + 10320) = hv; *(u64t*)(sm + off + 10320 + 20480) = lv; }

#define BUILD_STAGE(stage) { \
    BUILD_ONE(stage, rb, sA0, sA1, sA2, sA3); \
    BUILD_ONE(stage, rb + 32, sB0, sB1, sB2, sB3); }

#define CPASYNC_B(stage, kcv) { \
    u64t gs = gprep + (u64t)(kcv) * 24576; \
    u32 db = b_sm + (u32)(stage) * B_STAGE; \
    _Pragma("unroll") \
    for (int j = 0; j < 6; j++) { \
        u32 i = (u32)ptid * 16 + (u32)j * 4096; \
        asm volatile("cp.async.cg.shared.global [%0], [%1], 16;" \
                     :: "r"(db + i), "l"(gs + i) : "memory"); \
    } \
    asm volatile("cp.async.commit_group;" ::: "memory"); }

    // ---- prologue ----
    if (!is_cons) {
        LOAD_STAGE(0);
        BUILD_STAGE(0);
        CPASYNC_B(0, 0);
        LOAD_STAGE(1);
        asm volatile("cp.async.wait_group 0;" ::: "memory");
    } else {
        // consumers load tail weights while producers fill stage 0
        for (int i = tid; i < 4608; i += 256) { wf[OW2E + i] = eW2[i]; wf[OW2S + i] = sW2[i]; }
        for (int i = tid; i < 1152; i += 256) { wf[OW3E + i] = eW3[i]; wf[OW3S + i] = sW3[i]; }
        if (tid < 144) { wf[OW4E + tid] = eW4[tid]; wf[OW4E + 144 + tid] = eW4[144 + tid];
                         wf[OW4S + tid] = sW4[tid]; wf[OW4S + 144 + tid] = sW4[144 + tid]; }
        if (tid >= 160 && tid < 184) wf[OW5 + tid - 160] = sW5[tid - 160];
        if (tid >= 192 && tid < 204) {
            int k = tid - 192; float s = 0.f;
#pragma unroll
            for (int h = 0; h < 8; h++) s += eW5[h * 12 + k];
            wf[OE5 + k] = s;
        }
    }
    __syncthreads();

    // ---- mainloop ----
    for (int kc = 0; kc < 24; kc++) {
        const int cur = kc & 1, nxt = cur ^ 1;

        if (!is_cons) {
            // producers: fill next stage while consumers chew on cur
            if (kc < 23) {
                BUILD_STAGE(nxt);
                CPASYNC_B(nxt, kc + 1);
                if (kc < 22) { LOAD_STAGE(kc + 2); }
                asm volatile("cp.async.wait_group 0;" ::: "memory");
            }
        } else {
            const u32 a_hi = (u32)cur * 40960 + (u32)(mb0 * 16 + fr) * 80 + (u32)ql * 4;
            const u32 bbase = (u32)(SM_B0 + cur * B_STAGE + br * 12288)
                            + (u32)fr * 128 + (u32)ql * 16;
#pragma unroll
            for (int ks = 0; ks < 2; ks++) {
                u32 ao0 = a_hi + (u32)ks * 32;
                u32 ao1 = ao0 + 1280;     // mb0+1 (16 rows * 80B)
                u32 ah[2][4], al[2][4];
                ah[0][0] = *(const u32*)(sm + ao0);        ah[0][1] = *(const u32*)(sm + ao0 + 640);
                ah[0][2] = *(const u32*)(sm + ao0 + 16);   ah[0][3] = *(const u32*)(sm + ao0 + 656);
                al[0][0] = *(const u32*)(sm + ao0 + 20480); al[0][1] = *(const u32*)(sm + ao0 + 21120);
                al[0][2] = *(const u32*)(sm + ao0 + 20496); al[0][3] = *(const u32*)(sm + ao0 + 21136);
                ah[1][0] = *(const u32*)(sm + ao1);        ah[1][1] = *(const u32*)(sm + ao1 + 640);
                ah[1][2] = *(const u32*)(sm + ao1 + 16);   ah[1][3] = *(const u32*)(sm + ao1 + 656);
                al[1][0] = *(const u32*)(sm + ao1 + 20480); al[1][1] = *(const u32*)(sm + ao1 + 21120);
                al[1][2] = *(const u32*)(sm + ao1 + 20496); al[1][3] = *(const u32*)(sm + ao1 + 21136);
                u32 bsw = bbase + (u32)((ks ^ (fr & 1)) << 6);
#pragma unroll
                for (int nf = 0; nf < 12; nf++) {
                    uint4 bv = *(const uint4*)(sm + bsw + nf * 1024);
#pragma unroll
                    for (int im = 0; im < 2; im++) {
                        mma_bf16(acc[im][nf], ah[im][0], ah[im][1], ah[im][2], ah[im][3], bv.x, bv.y);
                        mma_bf16(acc[im][nf], al[im][0], al[im][1], al[im][2], al[im][3], bv.x, bv.y);
                        mma_bf16(acc[im][nf], ah[im][0], ah[im][1], ah[im][2], ah[im][3], bv.z, bv.w);
                    }
                }
            }
        }
        __syncthreads();
    }

    // ---- epilogue: relu(y1) -> [256][100] (overlays dead stage smem) ----
    if (is_cons) {
#pragma unroll
        for (int im = 0; im < 2; im++) {
            int m0 = (mb0 + im) * 16 + fr;
            int m1 = m0 + 8;
#pragma unroll
            for (int nf = 0; nf < 12; nf++) {
                int nb = nf * 8 + ql * 2;
                *(u64t*)(y1f + m0 * 100 + nb) = pack2(fmaxf(acc[im][nf][0], 0.f), fmaxf(acc[im][nf][1], 0.f));
                *(u64t*)(y1f + m1 * 100 + nb) = pack2(fmaxf(acc[im][nf][2], 0.f), fmaxf(acc[im][nf][3], 0.f));
            }
        }
    }
    __syncthreads();

    // ---- tail: 2 threads per vector, k-split + shfl combine ----
    {
        const int m  = tid >> 1;           // 0..255
        const int kh = tid & 1;            // k half
        const bool is_e = m < 128;
        const int r  = (m & 127) >> 1;
        const int vp = m & 1;

        u64t x[24];
        const u64t* xr = (const u64t*)(y1f + m * 100 + kh * 48);
#pragma unroll
        for (int i = 0; i < 24; i++) x[i] = xr[i];

        const float* W2 = wf + (is_e ? OW2E : OW2S) + kh * 48;
        float y2r[48];
#pragma unroll 4
        for (int n = 0; n < 48; n++) {
            const u64t* wr = (const u64t*)(W2 + n * 96);
            u64t s0 = 0, s1 = 0;
#pragma unroll
            for (int kp = 0; kp < 24; kp += 2) {
                s0 = fma2(x[kp], wr[kp], s0);
                s1 = fma2(x[kp + 1], wr[kp + 1], s1);
            }
            float s = red2(s0) + red2(s1);
            s += __shfl_xor_sync(0xffffffffu, s, 1);
            y2r[n] = fmaxf(s, 0.f);
        }

        u64t b2[12];
#pragma unroll
        for (int j = 0; j < 12; j++) b2[j] = pack2(y2r[kh * 24 + 2 * j], y2r[kh * 24 + 2 * j + 1]);
        const float* W3 = wf + (is_e ? OW3E : OW3S) + kh * 24;
        float y3r[24];
#pragma unroll
        for (int n = 0; n < 24; n++) {
            const u64t* wr = (const u64t*)(W3 + n * 48);
            u64t s0 = 0;
#pragma unroll
            for (int kp = 0; kp < 12; kp++) s0 = fma2(b2[kp], wr[kp], s0);
            float s = red2(s0);
            s += __shfl_xor_sync(0xffffffffu, s, 1);
            y3r[n] = fmaxf(s, 0.f);
        }

        u64t b3[6];
#pragma unroll
        for (int j = 0; j < 6; j++) b3[j] = pack2(y3r[kh * 12 + 2 * j], y3r[kh * 12 + 2 * j + 1]);
        const float* W4 = wf + (is_e ? OW4E : OW4S) + kh * 12;
        float r4[12];
#pragma unroll
        for (int n = 0; n < 12; n++) {
            const u64t* wr = (const u64t*)(W4 + n * 24);
            u64t s0 = 0;
#pragma unroll
            for (int kp = 0; kp < 6; kp++) s0 = fma2(b3[kp], wr[kp], s0);
            float s = red2(s0);
            s += __shfl_xor_sync(0xffffffffu, s, 1);
            r4[n] = fmaxf(s, 0.f);       // relu before W5
        }

        if (kh == 0) {
            const int idx2 = r * 2 + vp;
            if (is_e) {
                float Se = 0.f;
#pragma unroll
                for (int k = 0; k < 12; k++) Se = fmaf(r4[k], wf[OE5 + k], Se);
                wf[OSE + idx2] = Se;
            } else {
                float t0 = 0.f, t1 = 0.f;
#pragma unroll
                for (int k = 0; k < 12; k++) {
                    t0 = fmaf(r4[k], wf[OW5 + k], t0);
                    t1 = fmaf(r4[k], wf[OW5 + 12 + k], t1);
                }
                wf[OT0 + idx2] = t0;
                wf[OT1 + idx2] = t1;
            }
        }
    }
    __syncthreads();

    if (tid < 64) {
        const int r = tid;
        const float cw0 = cross_w[0], cw1 = cross_w[1];
        float SeP = wf[OSE + 2*r], SeS = wf[OSE + 2*r + 1];
        float o0 = cw0 * SeP * wf[OT0 + 2*r] + cw1 * SeS * wf[OT0 + 2*r + 1];
        float o1 = cw0 * SeP * wf[OT1 + 2*r] + cw1 * SeS * wf[OT1 + 2*r + 1];
        out[(size_t)(r0g + r) * 2 + 0] = o0;
        out[(size_t)(r0g + r) * 2 + 1] = o1;
    }
}

// ============================================================================
extern "C" void kernel_launch(void* const* d_in, const int* in_sizes, int n_in,
                              void* d_out, int out_size)
{
    const float* in      = (const float*)d_in[0];
    const float* sW1     = (const float*)d_in[1];
    const float* sW2     = (const float*)d_in[2];
    const float* sW3     = (const float*)d_in[3];
    const float* sW4     = (const float*)d_in[4];
    const float* sW5     = (const float*)d_in[5];
    const float* eW1     = (const float*)d_in[6];
    const float* eW2     = (const float*)d_in[7];
    const float* eW3     = (const float*)d_in[8];
    const float* eW4     = (const float*)d_in[9];
    const float* eW5     = (const float*)d_in[10];
    const float* s_seq   = (const float*)d_in[11];
    const float* s_pair  = (const float*)d_in[12];
    const float* e_seq   = (const float*)d_in[13];
    const float* e_pair  = (const float*)d_in[14];
    const float* cross_w = (const float*)d_in[15];
    float* out = (float*)d_out;

    const int B = in_sizes[0] / 3072;   // 65536

    static int init_done = 0;
    if (!init_done) {
        cudaFuncSetAttribute(fused_mma, cudaFuncAttributeMaxDynamicSharedMemorySize, SMEM_BYTES);
        init_done = 1;
    }
    prep_w1<<<144, 256>>>(eW1, sW1);
    fused_mma<<<B / 64, 512, SMEM_BYTES>>>(
        in, sW2, sW3, sW4, sW5, eW2, eW3, eW4, eW5,
        s_seq, s_pair, e_seq, e_pair, cross_w, out);
}

// round 8
// speedup vs baseline: 1.1530x; 1.1530x over previous
#include <cuda_runtime.h>
#include <cuda_bf16.h>
#include <cstdint>

typedef unsigned int u32;
typedef unsigned long long u64t;

// ============================================================================
// g_prep: packed, fragment-ordered, bank-swizzled hi/lo bf16 split of W1.
// [kc 0..23][br 0..1][n 0..95][ks^(n&1)][q] -> 16B {bh0,bh1,bl0,bl1}
// ============================================================================
__device__ __align__(16) u32 g_prep[24 * 2 * 96 * 32];   // 589824 B

__device__ __forceinline__ u32 pack_bf16(float a, float b) {
    __nv_bfloat162 h = __floats2bfloat162_rn(a, b);
    return *(u32*)&h;
}

__global__ void prep_w1(const float* __restrict__ eW1, const float* __restrict__ sW1)
{
    int idx = blockIdx.x * 256 + threadIdx.x;        // 0 .. 36863
    if (idx >= 36864) return;
    int q  = idx & 3;
    int ks = (idx >> 2) & 1;
    int n  = (idx >> 3) % 96;
    int t  = (idx >> 3) / 96;
    int kc = t % 24;
    int br = t / 24;
    const float* W = (br ? sW1 : eW1) + (size_t)n * 768 + kc * 32 + ks * 16;
    float x0 = W[2*q], x1 = W[2*q+1], x2 = W[8+2*q], x3 = W[8+2*q+1];
    float h0 = __bfloat162float(__float2bfloat16(x0));
    float h1 = __bfloat162float(__float2bfloat16(x1));
    float h2 = __bfloat162float(__float2bfloat16(x2));
    float h3 = __bfloat162float(__float2bfloat16(x3));
    uint4 v;
    v.x = pack_bf16(x0, x1);
    v.y = pack_bf16(x2, x3);
    v.z = pack_bf16(x0 - h0, x1 - h1);
    v.w = pack_bf16(x2 - h2, x3 - h3);
    u32 off = (u32)kc * 24576 + (u32)br * 12288 + (u32)n * 128
            + (u32)((ks ^ (n & 1)) << 6) + (u32)q * 16;
    *(uint4*)((char*)g_prep + off) = v;
}

// ============================================================================
// helpers
// ============================================================================
__device__ __forceinline__ u32 smem_u32(const void* p) {
    u32 a;
    asm("{ .reg .u64 t; cvta.to.shared.u64 t, %1; cvt.u32.u64 %0, t; }" : "=r"(a) : "l"(p));
    return a;
}
__device__ __forceinline__ u64t fma2(u64t a, u64t b, u64t c) {
    u64t d;
    asm("fma.rn.f32x2 %0, %1, %2, %3;" : "=l"(d) : "l"(a), "l"(b), "l"(c));
    return d;
}
__device__ __forceinline__ float red2(u64t v) {
    return __uint_as_float((u32)v) + __uint_as_float((u32)(v >> 32));
}
__device__ __forceinline__ u64t pack2(float lo, float hi) {
    return (u64t)__float_as_uint(lo) | ((u64t)__float_as_uint(hi) << 32);
}
__device__ __forceinline__ void split4(float4 q, u64t& hv, u64t& lv) {
    __nv_bfloat162 h01 = __floats2bfloat162_rn(q.x, q.y);
    __nv_bfloat162 h23 = __floats2bfloat162_rn(q.z, q.w);
    float2 f01 = __bfloat1622float2(h01);
    float2 f23 = __bfloat1622float2(h23);
    __nv_bfloat162 l01 = __floats2bfloat162_rn(q.x - f01.x, q.y - f01.y);
    __nv_bfloat162 l23 = __floats2bfloat162_rn(q.z - f23.x, q.w - f23.y);
    hv = (u64t)(*(u32*)&h01) | ((u64t)(*(u32*)&h23) << 32);
    lv = (u64t)(*(u32*)&l01) | ((u64t)(*(u32*)&l23) << 32);
}
__device__ __forceinline__ void mma_bf16(float c[4], u32 a0, u32 a1, u32 a2, u32 a3,
                                         u32 b0, u32 b1) {
    asm volatile("mma.sync.aligned.m16n8k16.row.col.f32.bf16.bf16.f32 "
        "{%0,%1,%2,%3}, {%4,%5,%6,%7}, {%8,%9}, {%0,%1,%2,%3};"
        : "+f"(c[0]), "+f"(c[1]), "+f"(c[2]), "+f"(c[3])
        : "r"(a0), "r"(a1), "r"(a2), "r"(a3), "r"(b0), "r"(b1));
}

// ============================================================================
// smem layout (bytes)
//   A stages: stage*40960, hi at +0 (256 rows * 80B), lo at +20480
//   B stages: 81920 + stage*24576
//   weights:  131072 (12516 floats)
//   tail y1 overlays [0, 102400): 256 rows * 100 f
// ============================================================================
#define SM_B0   81920
#define B_STAGE 24576
#define SM_W    131072
#define SMEM_BYTES 181248
// weight region float offsets
#define OW2E 0
#define OW2S 4608
#define OW3E 9216
#define OW3S 10368
#define OW4E 11520
#define OW4S 11808
#define OW5  12096
#define OE5  12120
#define OSE  12132
#define OT0  12260
#define OT1  12388

__global__ __launch_bounds__(512, 1) void fused_mma(
    const float* __restrict__ in,
    const float* __restrict__ sW2, const float* __restrict__ sW3,
    const float* __restrict__ sW4, const float* __restrict__ sW5,
    const float* __restrict__ eW2, const float* __restrict__ eW3,
    const float* __restrict__ eW4, const float* __restrict__ eW5,
    const float* __restrict__ s_seq, const float* __restrict__ s_pair,
    const float* __restrict__ e_seq, const float* __restrict__ e_pair,
    const float* __restrict__ cross_w,
    float* __restrict__ out)
{
    extern __shared__ __align__(1024) char sm[];
    float* wf  = (float*)(sm + SM_W);
    float* y1f = (float*)sm;

    const int tid = threadIdx.x;
    const int r0g = blockIdx.x * 64;

    const float ep0 = e_pair[0], ep1 = e_pair[1];
    const float sp0 = s_pair[0], sp1 = s_pair[1];
    const float es0 = e_seq[0], es1 = e_seq[1], es2 = e_seq[2], es3 = e_seq[3];
    const float ss0 = s_seq[0], ss1 = s_seq[1], ss2 = s_seq[2], ss3 = s_seq[3];

    // ---- builder mapping: one 64-row unit across 512 threads ----
    const int rb = tid >> 3;           // 0..63 batch row
    const int sk = tid & 7;            // float4 group within 32-k chunk
    const float* inp0 = in + (size_t)(r0g + rb) * 3072 + sk * 4;

    // ---- mma mapping: 16 warps, warp = m32 x n48 ----
    const int lane = tid & 31;
    const int w    = tid >> 5;          // 0..15
    const int br   = w >> 3;            // 0=e (w 0-7), 1=s (w 8-15)
    const int wm   = (w >> 1) & 3;      // m32 group within branch
    const int nh   = w & 1;             // n half (48 cols)
    const int fr   = lane >> 2;
    const int ql   = lane & 3;
    const int mb0  = br * 8 + wm * 2;   // first m16 block

    u64t gprep;
    asm("cvta.to.global.u64 %0, %1;" : "=l"(gprep) : "l"((const void*)g_prep));
    const u32 b_sm = smem_u32(sm + SM_B0);

    float acc[2][6][4];
#pragma unroll
    for (int im = 0; im < 2; im++)
#pragma unroll
        for (int nf = 0; nf < 6; nf++)
#pragma unroll
            for (int c = 0; c < 4; c++) acc[im][nf][c] = 0.f;

    float4 sA0, sA1, sA2, sA3;

#define LOAD_STAGE(kcv) { \
    const float* p0 = inp0 + (kcv) * 32; \
    sA0 = *(const float4*)p0; sA1 = *(const float4*)(p0 + 768); \
    sA2 = *(const float4*)(p0 + 1536); sA3 = *(const float4*)(p0 + 2304); }

#define BUILD_STAGE(stage) { \
    u32 off = (u32)(stage) * 40960 + (u32)rb * 160 + (u32)sk * 8; \
    float4 q; u64t hv, lv; \
    q.x = fmaxf(ep0*sA0.x + ep1*sA2.x, 0.f); q.y = fmaxf(ep0*sA0.y + ep1*sA2.y, 0.f); \
    q.z = fmaxf(ep0*sA0.z + ep1*sA2.z, 0.f); q.w = fmaxf(ep0*sA0.w + ep1*sA2.w, 0.f); \
    split4(q, hv, lv); \
    *(u64t*)(sm + off) = hv; *(u64t*)(sm + off + 20480) = lv; \
    q.x = fmaxf(es0*sA0.x + es1*sA1.x + es2*sA2.x + es3*sA3.x, 0.f); \
    q.y = fmaxf(es0*sA0.y + es1*sA1.y + es2*sA2.y + es3*sA3.y, 0.f); \
    q.z = fmaxf(es0*sA0.z + es1*sA1.z + es2*sA2.z + es3*sA3.z, 0.f); \
    q.w = fmaxf(es0*sA0.w + es1*sA1.w + es2*sA2.w + es3*sA3.w, 0.f); \
    split4(q, hv, lv); \
    *(u64t*)(sm + off + 80) = hv; *(u64t*)(sm + off + 80 + 20480) = lv; \
    q.x = fmaxf(sp0*sA0.x + sp1*sA2.x, 0.f); q.y = fmaxf(sp0*sA0.y + sp1*sA2.y, 0.f); \
    q.z = fmaxf(sp0*sA0.z + sp1*sA2.z, 0.f); q.w = fmaxf(sp0*sA0.w + sp1*sA2.w, 0.f); \
    split4(q, hv, lv); \
    *(u64t*)(sm + off + 10240) = hv; *(u64t*)(sm + off + 10240 + 20480) = lv; \
    q.x = fmaxf(ss0*sA0.x + ss1*sA1.x + ss2*sA2.x + ss3*sA3.x, 0.f); \
    q.y = fmaxf(ss0*sA0.y + ss1*sA1.y + ss2*sA2.y + ss3*sA3.y, 0.f); \
    q.z = fmaxf(ss0*sA0.z + ss1*sA1.z + ss2*sA2.z + ss3*sA3.z, 0.f); \
    q.w = fmaxf(ss0*sA0.w + ss1*sA1.w + ss2*sA2.w + ss3*sA3.w, 0.f); \
    split4(q, hv, lv); \
    *(u64t*)(sm + off + 10320) = hv; *(u64t*)(sm + off + 10320 + 20480) = lv; }

#define CPASYNC_B(stage, kcv) { \
    u64t gs = gprep + (u64t)(kcv) * 24576; \
    u32 db = b_sm + (u32)(stage) * B_STAGE; \
    _Pragma("unroll") \
    for (int j = 0; j < 3; j++) { \
        u32 i = (u32)tid * 16 + (u32)j * 8192; \
        asm volatile("cp.async.cg.shared.global [%0], [%1], 16;" \
                     :: "r"(db + i), "l"(gs + i) : "memory"); \
    } \
    asm volatile("cp.async.commit_group;" ::: "memory"); }

    // ---- prologue ----
    LOAD_STAGE(0);
    BUILD_STAGE(0);
    CPASYNC_B(0, 0);
    LOAD_STAGE(1);

    // tail weights (disjoint region; overlap with first-stage latency)
    for (int i = tid; i < 4608; i += 512) { wf[OW2E + i] = eW2[i]; wf[OW2S + i] = sW2[i]; }
    for (int i = tid; i < 1152; i += 512) { wf[OW3E + i] = eW3[i]; wf[OW3S + i] = sW3[i]; }
    if (tid < 288) { wf[OW4E + tid] = eW4[tid]; wf[OW4S + tid] = sW4[tid]; }
    if (tid >= 288 && tid < 312) wf[OW5 + tid - 288] = sW5[tid - 288];
    if (tid >= 320 && tid < 332) {
        int k = tid - 320; float s = 0.f;
#pragma unroll
        for (int h = 0; h < 8; h++) s += eW5[h * 12 + k];
        wf[OE5 + k] = s;
    }

    // ---- mainloop ----
    for (int kc = 0; kc < 24; kc++) {
        const int cur = kc & 1, nxt = cur ^ 1;
        asm volatile("cp.async.wait_group 0;" ::: "memory");
        __syncthreads();
        if (kc < 23) { BUILD_STAGE(nxt); CPASYNC_B(nxt, kc + 1); }
        if (kc < 22) { LOAD_STAGE(kc + 2); }

        const u32 a_hi = (u32)cur * 40960 + (u32)(mb0 * 16 + fr) * 80 + (u32)ql * 4;
        const u32 bbase = (u32)(SM_B0 + cur * B_STAGE + br * 12288 + nh * 6144)
                        + (u32)fr * 128 + (u32)ql * 16;
#pragma unroll
        for (int ks = 0; ks < 2; ks++) {
            u32 ao0 = a_hi + (u32)ks * 32;
            u32 ao1 = ao0 + 1280;     // mb0+1 (16 rows * 80B)
            u32 ah[2][4], al[2][4];
            ah[0][0] = *(const u32*)(sm + ao0);        ah[0][1] = *(const u32*)(sm + ao0 + 640);
            ah[0][2] = *(const u32*)(sm + ao0 + 16);   ah[0][3] = *(const u32*)(sm + ao0 + 656);
            al[0][0] = *(const u32*)(sm + ao0 + 20480); al[0][1] = *(const u32*)(sm + ao0 + 21120);
            al[0][2] = *(const u32*)(sm + ao0 + 20496); al[0][3] = *(const u32*)(sm + ao0 + 21136);
            ah[1][0] = *(const u32*)(sm + ao1);        ah[1][1] = *(const u32*)(sm + ao1 + 640);
            ah[1][2] = *(const u32*)(sm + ao1 + 16);   ah[1][3] = *(const u32*)(sm + ao1 + 656);
            al[1][0] = *(const u32*)(sm + ao1 + 20480); al[1][1] = *(const u32*)(sm + ao1 + 21120);
            al[1][2] = *(const u32*)(sm + ao1 + 20496); al[1][3] = *(const u32*)(sm + ao1 + 21136);
            u32 bsw = bbase + (u32)((ks ^ (fr & 1)) << 6);
#pragma unroll
            for (int nf = 0; nf < 6; nf++) {
                uint4 bv = *(const uint4*)(sm + bsw + nf * 1024);
#pragma unroll
                for (int im = 0; im < 2; im++) {
                    mma_bf16(acc[im][nf], ah[im][0], ah[im][1], ah[im][2], ah[im][3], bv.x, bv.y);
                    mma_bf16(acc[im][nf], al[im][0], al[im][1], al[im][2], al[im][3], bv.x, bv.y);
                    mma_bf16(acc[im][nf], ah[im][0], ah[im][1], ah[im][2], ah[im][3], bv.z, bv.w);
                }
            }
        }
    }
    __syncthreads();   // mainloop smem dead; overlay y1

    // ---- epilogue: relu(y1) -> [256][100] ----
#pragma unroll
    for (int im = 0; im < 2; im++) {
        int m0 = (mb0 + im) * 16 + fr;
        int m1 = m0 + 8;
#pragma unroll
        for (int nf = 0; nf < 6; nf++) {
            int nb = (nh * 6 + nf) * 8 + ql * 2;
            *(u64t*)(y1f + m0 * 100 + nb) = pack2(fmaxf(acc[im][nf][0], 0.f), fmaxf(acc[im][nf][1], 0.f));
            *(u64t*)(y1f + m1 * 100 + nb) = pack2(fmaxf(acc[im][nf][2], 0.f), fmaxf(acc[im][nf][3], 0.f));
        }
    }
    __syncthreads();

    // ---- tail: 2 threads per vector, k-split + shfl combine ----
    {
        const int m  = tid >> 1;           // 0..255
        const int kh = tid & 1;            // k half
        const bool is_e = m < 128;
        const int r  = (m & 127) >> 1;
        const int vp = m & 1;

        u64t x[24];
        const u64t* xr = (const u64t*)(y1f + m * 100 + kh * 48);
#pragma unroll
        for (int i = 0; i < 24; i++) x[i] = xr[i];

        const float* W2 = wf + (is_e ? OW2E : OW2S) + kh * 48;
        float y2r[48];
#pragma unroll 4
        for (int n = 0; n < 48; n++) {
            const u64t* wr = (const u64t*)(W2 + n * 96);
            u64t s0 = 0, s1 = 0;
#pragma unroll
            for (int kp = 0; kp < 24; kp += 2) {
                s0 = fma2(x[kp], wr[kp], s0);
                s1 = fma2(x[kp + 1], wr[kp + 1], s1);
            }
            float s = red2(s0) + red2(s1);
            s += __shfl_xor_sync(0xffffffffu, s, 1);
            y2r[n] = fmaxf(s, 0.f);
        }

        u64t b2[12];
#pragma unroll
        for (int j = 0; j < 12; j++) b2[j] = pack2(y2r[kh * 24 + 2 * j], y2r[kh * 24 + 2 * j + 1]);
        const float* W3 = wf + (is_e ? OW3E : OW3S) + kh * 24;
        float y3r[24];
#pragma unroll
        for (int n = 0; n < 24; n++) {
            const u64t* wr = (const u64t*)(W3 + n * 48);
            u64t s0 = 0;
#pragma unroll
            for (int kp = 0; kp < 12; kp++) s0 = fma2(b2[kp], wr[kp], s0);
            float s = red2(s0);
            s += __shfl_xor_sync(0xffffffffu, s, 1);
            y3r[n] = fmaxf(s, 0.f);
        }

        u64t b3[6];
#pragma unroll
        for (int j = 0; j < 6; j++) b3[j] = pack2(y3r[kh * 12 + 2 * j], y3r[kh * 12 + 2 * j + 1]);
        const float* W4 = wf + (is_e ? OW4E : OW4S) + kh * 12;
        float r4[12];
#pragma unroll
        for (int n = 0; n < 12; n++) {
            const u64t* wr = (const u64t*)(W4 + n * 24);
            u64t s0 = 0;
#pragma unroll
            for (int kp = 0; kp < 6; kp++) s0 = fma2(b3[kp], wr[kp], s0);
            float s = red2(s0);
            s += __shfl_xor_sync(0xffffffffu, s, 1);
            r4[n] = fmaxf(s, 0.f);       // relu before W5
        }

        if (kh == 0) {
            const int idx2 = r * 2 + vp;
            if (is_e) {
                float Se = 0.f;
#pragma unroll
                for (int k = 0; k < 12; k++) Se = fmaf(r4[k], wf[OE5 + k], Se);
                wf[OSE + idx2] = Se;
            } else {
                float t0 = 0.f, t1 = 0.f;
#pragma unroll
                for (int k = 0; k < 12; k++) {
                    t0 = fmaf(r4[k], wf[OW5 + k], t0);
                    t1 = fmaf(r4[k], wf[OW5 + 12 + k], t1);
                }
                wf[OT0 + idx2] = t0;
                wf[OT1 + idx2] = t1;
            }
        }
    }
    __syncthreads();

    if (tid < 64) {
        const int r = tid;
        const float cw0 = cross_w[0], cw1 = cross_w[1];
        float SeP = wf[OSE + 2*r], SeS = wf[OSE + 2*r + 1];
        float o0 = cw0 * SeP * wf[OT0 + 2*r] + cw1 * SeS * wf[OT0 + 2*r + 1];
        float o1 = cw0 * SeP * wf[OT1 + 2*r] + cw1 * SeS * wf[OT1 + 2*r + 1];
        out[(size_t)(r0g + r) * 2 + 0] = o0;
        out[(size_t)(r0g + r) * 2 + 1] = o1;
    }
}

// ============================================================================
extern "C" void kernel_launch(void* const* d_in, const int* in_sizes, int n_in,
                              void* d_out, int out_size)
{
    const float* in      = (const float*)d_in[0];
    const float* sW1     = (const float*)d_in[1];
    const float* sW2     = (const float*)d_in[2];
    const float* sW3     = (const float*)d_in[3];
    const float* sW4     = (const float*)d_in[4];
    const float* sW5     = (const float*)d_in[5];
    const float* eW1     = (const float*)d_in[6];
    const float* eW2     = (const float*)d_in[7];
    const float* eW3     = (const float*)d_in[8];
    const float* eW4     = (const float*)d_in[9];
    const float* eW5     = (const float*)d_in[10];
    const float* s_seq   = (const float*)d_in[11];
    const float* s_pair  = (const float*)d_in[12];
    const float* e_seq   = (const float*)d_in[13];
    const float* e_pair  = (const float*)d_in[14];
    const float* cross_w = (const float*)d_in[15];
    float* out = (float*)d_out;

    const int B = in_sizes[0] / 3072;   // 65536

    static int init_done = 0;
    if (!init_done) {
        cudaFuncSetAttribute(fused_mma, cudaFuncAttributeMaxDynamicSharedMemorySize, SMEM_BYTES);
        init_done = 1;
    }
    prep_w1<<<144, 256>>>(eW1, sW1);
    fused_mma<<<B / 64, 512, SMEM_BYTES>>>(
        in, sW2, sW3, sW4, sW5, eW2, eW3, eW4, eW5,
        s_seq, s_pair, e_seq, e_pair, cross_w, out);
}

// round 9
// speedup vs baseline: 1.1860x; 1.0287x over previous
#include <cuda_runtime.h>
#include <cuda_bf16.h>
#include <cstdint>

typedef unsigned int u32;
typedef unsigned long long u64t;

// ============================================================================
// g_prep: packed, fragment-ordered, bank-swizzled hi/lo bf16 split of W1.
// [kc 0..23][br 0..1][n 0..95][ks^(n&1)][q] -> 16B {bh0,bh1,bl0,bl1}
// ============================================================================
__device__ __align__(16) u32 g_prep[24 * 2 * 96 * 32];   // 589824 B

__device__ __forceinline__ u32 pack_bf16(float a, float b) {
    __nv_bfloat162 h = __floats2bfloat162_rn(a, b);
    return *(u32*)&h;
}

__global__ void prep_w1(const float* __restrict__ eW1, const float* __restrict__ sW1)
{
    int idx = blockIdx.x * 256 + threadIdx.x;        // 0 .. 36863
    if (idx >= 36864) return;
    int q  = idx & 3;
    int ks = (idx >> 2) & 1;
    int n  = (idx >> 3) % 96;
    int t  = (idx >> 3) / 96;
    int kc = t % 24;
    int br = t / 24;
    const float* W = (br ? sW1 : eW1) + (size_t)n * 768 + kc * 32 + ks * 16;
    float x0 = W[2*q], x1 = W[2*q+1], x2 = W[8+2*q], x3 = W[8+2*q+1];
    float h0 = __bfloat162float(__float2bfloat16(x0));
    float h1 = __bfloat162float(__float2bfloat16(x1));
    float h2 = __bfloat162float(__float2bfloat16(x2));
    float h3 = __bfloat162float(__float2bfloat16(x3));
    uint4 v;
    v.x = pack_bf16(x0, x1);
    v.y = pack_bf16(x2, x3);
    v.z = pack_bf16(x0 - h0, x1 - h1);
    v.w = pack_bf16(x2 - h2, x3 - h3);
    u32 off = (u32)kc * 24576 + (u32)br * 12288 + (u32)n * 128
            + (u32)((ks ^ (n & 1)) << 6) + (u32)q * 16;
    *(uint4*)((char*)g_prep + off) = v;
}

// ============================================================================
// helpers
// ============================================================================
__device__ __forceinline__ u32 smem_u32(const void* p) {
    u32 a;
    asm("{ .reg .u64 t; cvta.to.shared.u64 t, %1; cvt.u32.u64 %0, t; }" : "=r"(a) : "l"(p));
    return a;
}
__device__ __forceinline__ u64t fma2(u64t a, u64t b, u64t c) {
    u64t d;
    asm("fma.rn.f32x2 %0, %1, %2, %3;" : "=l"(d) : "l"(a), "l"(b), "l"(c));
    return d;
}
__device__ __forceinline__ float red2(u64t v) {
    return __uint_as_float((u32)v) + __uint_as_float((u32)(v >> 32));
}
__device__ __forceinline__ u64t pack2(float lo, float hi) {
    return (u64t)__float_as_uint(lo) | ((u64t)__float_as_uint(hi) << 32);
}
__device__ __forceinline__ void split4(float4 q, u64t& hv, u64t& lv) {
    __nv_bfloat162 h01 = __floats2bfloat162_rn(q.x, q.y);
    __nv_bfloat162 h23 = __floats2bfloat162_rn(q.z, q.w);
    float2 f01 = __bfloat1622float2(h01);
    float2 f23 = __bfloat1622float2(h23);
    __nv_bfloat162 l01 = __floats2bfloat162_rn(q.x - f01.x, q.y - f01.y);
    __nv_bfloat162 l23 = __floats2bfloat162_rn(q.z - f23.x, q.w - f23.y);
    hv = (u64t)(*(u32*)&h01) | ((u64t)(*(u32*)&h23) << 32);
    lv = (u64t)(*(u32*)&l01) | ((u64t)(*(u32*)&l23) << 32);
}
__device__ __forceinline__ void mma_bf16(float c[4], u32 a0, u32 a1, u32 a2, u32 a3,
                                         u32 b0, u32 b1) {
    asm volatile("mma.sync.aligned.m16n8k16.row.col.f32.bf16.bf16.f32 "
        "{%0,%1,%2,%3}, {%4,%5,%6,%7}, {%8,%9}, {%0,%1,%2,%3};"
        : "+f"(c[0]), "+f"(c[1]), "+f"(c[2]), "+f"(c[3])
        : "r"(a0), "r"(a1), "r"(a2), "r"(a3), "r"(b0), "r"(b1));
}
#define LDSM_X4(d0, d1, d2, d3, a) \
    asm volatile("ldmatrix.sync.aligned.m8n8.x4.shared.b16 {%0,%1,%2,%3}, [%4];" \
        : "=r"(d0), "=r"(d1), "=r"(d2), "=r"(d3) : "r"(a))

// ============================================================================
// smem layout (bytes)
//   A stages: stage*40960, hi at +0 (256 rows * 80B), lo at +20480
//   B stages: 81920 + stage*24576
//   weights:  131072 (12516 floats)
//   tail y1 overlays [0, 102400): 256 rows * 100 f
// ============================================================================
#define SM_B0   81920
#define B_STAGE 24576
#define SM_W    131072
#define SMEM_BYTES 181248
// weight region float offsets
#define OW2E 0
#define OW2S 4608
#define OW3E 9216
#define OW3S 10368
#define OW4E 11520
#define OW4S 11808
#define OW5  12096
#define OE5  12120
#define OSE  12132
#define OT0  12260
#define OT1  12388

__global__ __launch_bounds__(512, 1) void fused_mma(
    const float* __restrict__ in,
    const float* __restrict__ sW2, const float* __restrict__ sW3,
    const float* __restrict__ sW4, const float* __restrict__ sW5,
    const float* __restrict__ eW2, const float* __restrict__ eW3,
    const float* __restrict__ eW4, const float* __restrict__ eW5,
    const float* __restrict__ s_seq, const float* __restrict__ s_pair,
    const float* __restrict__ e_seq, const float* __restrict__ e_pair,
    const float* __restrict__ cross_w,
    float* __restrict__ out)
{
    extern __shared__ __align__(1024) char sm[];
    float* wf  = (float*)(sm + SM_W);
    float* y1f = (float*)sm;

    const int tid = threadIdx.x;
    const int r0g = blockIdx.x * 64;

    const float ep0 = e_pair[0], ep1 = e_pair[1];
    const float sp0 = s_pair[0], sp1 = s_pair[1];
    const float es0 = e_seq[0], es1 = e_seq[1], es2 = e_seq[2], es3 = e_seq[3];
    const float ss0 = s_seq[0], ss1 = s_seq[1], ss2 = s_seq[2], ss3 = s_seq[3];

    // ---- builder mapping ----
    const int rb = tid >> 3;           // 0..63 batch row
    const int sk = tid & 7;            // float4 group within 32-k chunk
    const float* inp0 = in + (size_t)(r0g + rb) * 3072 + sk * 4;

    // ---- mma mapping: 16 warps, warp = m32 x n48 ----
    const int lane = tid & 31;
    const int w    = tid >> 5;          // 0..15
    const int br   = w >> 3;            // 0=e, 1=s
    const int wm   = (w >> 1) & 3;
    const int nh   = w & 1;
    const int fr   = lane >> 2;
    const int ql   = lane & 3;
    const int mb0  = br * 8 + wm * 2;

    // ldmatrix lane addressing (canonical m16k16 x4)
    const u32 lrow = (u32)((lane & 7) | (((lane >> 3) & 1) << 3));   // 0..15
    const u32 lkb  = (u32)((lane >> 4) * 16);                        // 0 or 16 B

    u64t gprep;
    asm("cvta.to.global.u64 %0, %1;" : "=l"(gprep) : "l"((const void*)g_prep));
    const u32 smbase = smem_u32(sm);
    const u32 b_sm = smbase + SM_B0;

    float acc[2][6][4];
#pragma unroll
    for (int im = 0; im < 2; im++)
#pragma unroll
        for (int nf = 0; nf < 6; nf++)
#pragma unroll
            for (int c = 0; c < 4; c++) acc[im][nf][c] = 0.f;

    float4 sA0, sA1, sA2, sA3;

#define LOAD_STAGE(kcv) { \
    const float* p0 = inp0 + (kcv) * 32; \
    sA0 = *(const float4*)p0; sA1 = *(const float4*)(p0 + 768); \
    sA2 = *(const float4*)(p0 + 1536); sA3 = *(const float4*)(p0 + 2304); }

#define BUILD_STAGE(stage) { \
    u32 off = (u32)(stage) * 40960 + (u32)rb * 160 + (u32)sk * 8; \
    float4 q; u64t hv, lv; \
    q.x = fmaxf(ep0*sA0.x + ep1*sA2.x, 0.f); q.y = fmaxf(ep0*sA0.y + ep1*sA2.y, 0.f); \
    q.z = fmaxf(ep0*sA0.z + ep1*sA2.z, 0.f); q.w = fmaxf(ep0*sA0.w + ep1*sA2.w, 0.f); \
    split4(q, hv, lv); \
    *(u64t*)(sm + off) = hv; *(u64t*)(sm + off + 20480) = lv; \
    q.x = fmaxf(es0*sA0.x + es1*sA1.x + es2*sA2.x + es3*sA3.x, 0.f); \
    q.y = fmaxf(es0*sA0.y + es1*sA1.y + es2*sA2.y + es3*sA3.y, 0.f); \
    q.z = fmaxf(es0*sA0.z + es1*sA1.z + es2*sA2.z + es3*sA3.z, 0.f); \
    q.w = fmaxf(es0*sA0.w + es1*sA1.w + es2*sA2.w + es3*sA3.w, 0.f); \
    split4(q, hv, lv); \
    *(u64t*)(sm + off + 80) = hv; *(u64t*)(sm + off + 80 + 20480) = lv; \
    q.x = fmaxf(sp0*sA0.x + sp1*sA2.x, 0.f); q.y = fmaxf(sp0*sA0.y + sp1*sA2.y, 0.f); \
    q.z = fmaxf(sp0*sA0.z + sp1*sA2.z, 0.f); q.w = fmaxf(sp0*sA0.w + sp1*sA2.w, 0.f); \
    split4(q, hv, lv); \
    *(u64t*)(sm + off + 10240) = hv; *(u64t*)(sm + off + 10240 + 20480) = lv; \
    q.x = fmaxf(ss0*sA0.x + ss1*sA1.x + ss2*sA2.x + ss3*sA3.x, 0.f); \
    q.y = fmaxf(ss0*sA0.y + ss1*sA1.y + ss2*sA2.y + ss3*sA3.y, 0.f); \
    q.z = fmaxf(ss0*sA0.z + ss1*sA1.z + ss2*sA2.z + ss3*sA3.z, 0.f); \
    q.w = fmaxf(ss0*sA0.w + ss1*sA1.w + ss2*sA2.w + ss3*sA3.w, 0.f); \
    split4(q, hv, lv); \
    *(u64t*)(sm + off + 10320) = hv; *(u64t*)(sm + off + 10320 + 20480) = lv; }

#define CPASYNC_B(stage, kcv) { \
    u64t gs = gprep + (u64t)(kcv) * 24576; \
    u32 db = b_sm + (u32)(stage) * B_STAGE; \
    _Pragma("unroll") \
    for (int j = 0; j < 3; j++) { \
        u32 i = (u32)tid * 16 + (u32)j * 8192; \
        asm volatile("cp.async.cg.shared.global [%0], [%1], 16;" \
                     :: "r"(db + i), "l"(gs + i) : "memory"); \
    } \
    asm volatile("cp.async.commit_group;" ::: "memory"); }

// one k16 step of MMAs for both m-blocks, all 6 nf, 3 passes
#define MMA_KS(ks) { \
    u32 aB = smbase + (u32)cur * 40960 + (u32)(mb0 * 16 + lrow) * 80 + lkb + (u32)(ks) * 32; \
    u32 ah0[4], ah1[4], al0[4], al1[4]; \
    LDSM_X4(ah0[0], ah0[1], ah0[2], ah0[3], aB); \
    LDSM_X4(ah1[0], ah1[1], ah1[2], ah1[3], aB + 1280); \
    LDSM_X4(al0[0], al0[1], al0[2], al0[3], aB + 20480); \
    LDSM_X4(al1[0], al1[1], al1[2], al1[3], aB + 21760); \
    u32 bsw = bbase + (u32)(((ks) ^ (fr & 1)) << 6); \
    _Pragma("unroll") \
    for (int nf = 0; nf < 6; nf++) { \
        uint4 bv = *(const uint4*)(sm + (bsw - smbase) + nf * 1024); \
        mma_bf16(acc[0][nf], ah0[0], ah0[1], ah0[2], ah0[3], bv.x, bv.y); \
        mma_bf16(acc[0][nf], al0[0], al0[1], al0[2], al0[3], bv.x, bv.y); \
        mma_bf16(acc[0][nf], ah0[0], ah0[1], ah0[2], ah0[3], bv.z, bv.w); \
        mma_bf16(acc[1][nf], ah1[0], ah1[1], ah1[2], ah1[3], bv.x, bv.y); \
        mma_bf16(acc[1][nf], al1[0], al1[1], al1[2], al1[3], bv.x, bv.y); \
        mma_bf16(acc[1][nf], ah1[0], ah1[1], ah1[2], ah1[3], bv.z, bv.w); \
    } }

    // ---- prologue ----
    LOAD_STAGE(0);
    BUILD_STAGE(0);
    CPASYNC_B(0, 0);
    LOAD_STAGE(1);

    // tail weights (disjoint region; overlap with first-stage latency)
    for (int i = tid; i < 4608; i += 512) { wf[OW2E + i] = eW2[i]; wf[OW2S + i] = sW2[i]; }
    for (int i = tid; i < 1152; i += 512) { wf[OW3E + i] = eW3[i]; wf[OW3S + i] = sW3[i]; }
    if (tid < 288) { wf[OW4E + tid] = eW4[tid]; wf[OW4S + tid] = sW4[tid]; }
    if (tid >= 288 && tid < 312) wf[OW5 + tid - 288] = sW5[tid - 288];
    if (tid >= 320 && tid < 332) {
        int k = tid - 320; float s = 0.f;
#pragma unroll
        for (int h = 0; h < 8; h++) s += eW5[h * 12 + k];
        wf[OE5 + k] = s;
    }

    asm volatile("cp.async.wait_group 0;" ::: "memory");
    __syncthreads();

    // ---- mainloop (branchless body: one basic block per chunk) ----
    for (int kc = 0; kc < 24; kc++) {
        const int cur = kc & 1, nxt = cur ^ 1;
        const int kn = (kc < 23) ? kc + 1 : 23;
        const int kl = (kc < 22) ? kc + 2 : 23;
        const u32 bbase = b_sm + (u32)cur * B_STAGE + (u32)(br * 12288 + nh * 6144)
                        + (u32)fr * 128 + (u32)ql * 16;

        CPASYNC_B(nxt, kn);        // B for next chunk: latency hides under body
        MMA_KS(0);
        BUILD_STAGE(nxt);          // A for next chunk (from prefetched regs)
        MMA_KS(1);
        LOAD_STAGE(kl);            // LDG prefetch for chunk kc+2
        asm volatile("cp.async.wait_group 0;" ::: "memory");
        __syncthreads();
    }

    // ---- epilogue: relu(y1) -> [256][100] ----
#pragma unroll
    for (int im = 0; im < 2; im++) {
        int m0 = (mb0 + im) * 16 + fr;
        int m1 = m0 + 8;
#pragma unroll
        for (int nf = 0; nf < 6; nf++) {
            int nb = (nh * 6 + nf) * 8 + ql * 2;
            *(u64t*)(y1f + m0 * 100 + nb) = pack2(fmaxf(acc[im][nf][0], 0.f), fmaxf(acc[im][nf][1], 0.f));
            *(u64t*)(y1f + m1 * 100 + nb) = pack2(fmaxf(acc[im][nf][2], 0.f), fmaxf(acc[im][nf][3], 0.f));
        }
    }
    __syncthreads();

    // ---- tail: 2 threads per vector, k-split + shfl combine ----
    {
        const int m  = tid >> 1;           // 0..255
        const int kh = tid & 1;            // k half
        const bool is_e = m < 128;
        const int r  = (m & 127) >> 1;
        const int vp = m & 1;

        u64t x[24];
        const u64t* xr = (const u64t*)(y1f + m * 100 + kh * 48);
#pragma unroll
        for (int i = 0; i < 24; i++) x[i] = xr[i];

        const float* W2 = wf + (is_e ? OW2E : OW2S) + kh * 48;
        float y2r[48];
#pragma unroll 4
        for (int n = 0; n < 48; n++) {
            const u64t* wr = (const u64t*)(W2 + n * 96);
            u64t s0 = 0, s1 = 0;
#pragma unroll
            for (int kp = 0; kp < 24; kp += 2) {
                s0 = fma2(x[kp], wr[kp], s0);
                s1 = fma2(x[kp + 1], wr[kp + 1], s1);
            }
            float s = red2(s0) + red2(s1);
            s += __shfl_xor_sync(0xffffffffu, s, 1);
            y2r[n] = fmaxf(s, 0.f);
        }

        u64t b2[12];
#pragma unroll
        for (int j = 0; j < 12; j++) b2[j] = pack2(y2r[kh * 24 + 2 * j], y2r[kh * 24 + 2 * j + 1]);
        const float* W3 = wf + (is_e ? OW3E : OW3S) + kh * 24;
        float y3r[24];
#pragma unroll
        for (int n = 0; n < 24; n++) {
            const u64t* wr = (const u64t*)(W3 + n * 48);
            u64t s0 = 0;
#pragma unroll
            for (int kp = 0; kp < 12; kp++) s0 = fma2(b2[kp], wr[kp], s0);
            float s = red2(s0);
            s += __shfl_xor_sync(0xffffffffu, s, 1);
            y3r[n] = fmaxf(s, 0.f);
        }

        u64t b3[6];
#pragma unroll
        for (int j = 0; j < 6; j++) b3[j] = pack2(y3r[kh * 12 + 2 * j], y3r[kh * 12 + 2 * j + 1]);
        const float* W4 = wf + (is_e ? OW4E : OW4S) + kh * 12;
        float r4[12];
#pragma unroll
        for (int n = 0; n < 12; n++) {
            const u64t* wr = (const u64t*)(W4 + n * 24);
            u64t s0 = 0;
#pragma unroll
            for (int kp = 0; kp < 6; kp++) s0 = fma2(b3[kp], wr[kp], s0);
            float s = red2(s0);
            s += __shfl_xor_sync(0xffffffffu, s, 1);
            r4[n] = fmaxf(s, 0.f);       // relu before W5
        }

        if (kh == 0) {
            const int idx2 = r * 2 + vp;
            if (is_e) {
                float Se = 0.f;
#pragma unroll
                for (int k = 0; k < 12; k++) Se = fmaf(r4[k], wf[OE5 + k], Se);
                wf[OSE + idx2] = Se;
            } else {
                float t0 = 0.f, t1 = 0.f;
#pragma unroll
                for (int k = 0; k < 12; k++) {
                    t0 = fmaf(r4[k], wf[OW5 + k], t0);
                    t1 = fmaf(r4[k], wf[OW5 + 12 + k], t1);
                }
                wf[OT0 + idx2] = t0;
                wf[OT1 + idx2] = t1;
            }
        }
    }
    __syncthreads();

    if (tid < 64) {
        const int r = tid;
        const float cw0 = cross_w[0], cw1 = cross_w[1];
        float SeP = wf[OSE + 2*r], SeS = wf[OSE + 2*r + 1];
        float o0 = cw0 * SeP * wf[OT0 + 2*r] + cw1 * SeS * wf[OT0 + 2*r + 1];
        float o1 = cw0 * SeP * wf[OT1 + 2*r] + cw1 * SeS * wf[OT1 + 2*r + 1];
        out[(size_t)(r0g + r) * 2 + 0] = o0;
        out[(size_t)(r0g + r) * 2 + 1] = o1;
    }
}

// ============================================================================
extern "C" void kernel_launch(void* const* d_in, const int* in_sizes, int n_in,
                              void* d_out, int out_size)
{
    const float* in      = (const float*)d_in[0];
    const float* sW1     = (const float*)d_in[1];
    const float* sW2     = (const float*)d_in[2];
    const float* sW3     = (const float*)d_in[3];
    const float* sW4     = (const float*)d_in[4];
    const float* sW5     = (const float*)d_in[5];
    const float* eW1     = (const float*)d_in[6];
    const float* eW2     = (const float*)d_in[7];
    const float* eW3     = (const float*)d_in[8];
    const float* eW4     = (const float*)d_in[9];
    const float* eW5     = (const float*)d_in[10];
    const float* s_seq   = (const float*)d_in[11];
    const float* s_pair  = (const float*)d_in[12];
    const float* e_seq   = (const float*)d_in[13];
    const float* e_pair  = (const float*)d_in[14];
    const float* cross_w = (const float*)d_in[15];
    float* out = (float*)d_out;

    const int B = in_sizes[0] / 3072;   // 65536

    static int init_done = 0;
    if (!init_done) {
        cudaFuncSetAttribute(fused_mma, cudaFuncAttributeMaxDynamicSharedMemorySize, SMEM_BYTES);
        init_done = 1;
    }
    prep_w1<<<144, 256>>>(eW1, sW1);
    fused_mma<<<B / 64, 512, SMEM_BYTES>>>(
        in, sW2, sW3, sW4, sW5, eW2, eW3, eW4, eW5,
        s_seq, s_pair, e_seq, e_pair, cross_w, out);
}

// round 10
// speedup vs baseline: 1.2590x; 1.0615x over previous
#include <cuda_runtime.h>
#include <cuda_bf16.h>
#include <cstdint>

typedef unsigned int u32;
typedef unsigned long long u64t;

// ============================================================================
// g_prep: packed, fragment-ordered, bank-swizzled hi/lo bf16 split of W1.
// [kc 0..23][br 0..1][n 0..95][ks^(n&1)][q] -> 16B {bh0,bh1,bl0,bl1}
// ============================================================================
__device__ __align__(16) u32 g_prep[24 * 2 * 96 * 32];   // 589824 B

__device__ __forceinline__ u32 pack_bf16(float a, float b) {
    __nv_bfloat162 h = __floats2bfloat162_rn(a, b);
    return *(u32*)&h;
}

__global__ void prep_w1(const float* __restrict__ eW1, const float* __restrict__ sW1)
{
    int idx = blockIdx.x * 256 + threadIdx.x;        // 0 .. 36863
    if (idx >= 36864) return;
    int q  = idx & 3;
    int ks = (idx >> 2) & 1;
    int n  = (idx >> 3) % 96;
    int t  = (idx >> 3) / 96;
    int kc = t % 24;
    int br = t / 24;
    const float* W = (br ? sW1 : eW1) + (size_t)n * 768 + kc * 32 + ks * 16;
    float x0 = W[2*q], x1 = W[2*q+1], x2 = W[8+2*q], x3 = W[8+2*q+1];
    float h0 = __bfloat162float(__float2bfloat16(x0));
    float h1 = __bfloat162float(__float2bfloat16(x1));
    float h2 = __bfloat162float(__float2bfloat16(x2));
    float h3 = __bfloat162float(__float2bfloat16(x3));
    uint4 v;
    v.x = pack_bf16(x0, x1);
    v.y = pack_bf16(x2, x3);
    v.z = pack_bf16(x0 - h0, x1 - h1);
    v.w = pack_bf16(x2 - h2, x3 - h3);
    u32 off = (u32)kc * 24576 + (u32)br * 12288 + (u32)n * 128
            + (u32)((ks ^ (n & 1)) << 6) + (u32)q * 16;
    *(uint4*)((char*)g_prep + off) = v;
}

// ============================================================================
// helpers
// ============================================================================
__device__ __forceinline__ u32 smem_u32(const void* p) {
    u32 a;
    asm("{ .reg .u64 t; cvta.to.shared.u64 t, %1; cvt.u32.u64 %0, t; }" : "=r"(a) : "l"(p));
    return a;
}
__device__ __forceinline__ u64t fma2(u64t a, u64t b, u64t c) {
    u64t d;
    asm("fma.rn.f32x2 %0, %1, %2, %3;" : "=l"(d) : "l"(a), "l"(b), "l"(c));
    return d;
}
__device__ __forceinline__ float red2(u64t v) {
    return __uint_as_float((u32)v) + __uint_as_float((u32)(v >> 32));
}
__device__ __forceinline__ u64t pack2(float lo, float hi) {
    return (u64t)__float_as_uint(lo) | ((u64t)__float_as_uint(hi) << 32);
}
__device__ __forceinline__ void split4(float4 q, u64t& hv, u64t& lv) {
    __nv_bfloat162 h01 = __floats2bfloat162_rn(q.x, q.y);
    __nv_bfloat162 h23 = __floats2bfloat162_rn(q.z, q.w);
    float2 f01 = __bfloat1622float2(h01);
    float2 f23 = __bfloat1622float2(h23);
    __nv_bfloat162 l01 = __floats2bfloat162_rn(q.x - f01.x, q.y - f01.y);
    __nv_bfloat162 l23 = __floats2bfloat162_rn(q.z - f23.x, q.w - f23.y);
    hv = (u64t)(*(u32*)&h01) | ((u64t)(*(u32*)&h23) << 32);
    lv = (u64t)(*(u32*)&l01) | ((u64t)(*(u32*)&l23) << 32);
}
__device__ __forceinline__ void mma_bf16(float c[4], u32 a0, u32 a1, u32 a2, u32 a3,
                                         u32 b0, u32 b1) {
    asm volatile("mma.sync.aligned.m16n8k16.row.col.f32.bf16.bf16.f32 "
        "{%0,%1,%2,%3}, {%4,%5,%6,%7}, {%8,%9}, {%0,%1,%2,%3};"
        : "+f"(c[0]), "+f"(c[1]), "+f"(c[2]), "+f"(c[3])
        : "r"(a0), "r"(a1), "r"(a2), "r"(a3), "r"(b0), "r"(b1));
}
#define LDSM_X4(d0, d1, d2, d3, a) \
    asm volatile("ldmatrix.sync.aligned.m8n8.x4.shared.b16 {%0,%1,%2,%3}, [%4];" \
        : "=r"(d0), "=r"(d1), "=r"(d2), "=r"(d3) : "r"(a))

// ============================================================================
// smem layout (bytes), per 256-thread CTA (2 CTAs/SM)
//   A stages: stage*20480; hi at +0 (128 vec rows * 80B), lo at +10240
//   B stages: 40960 + stage*24576  -> ends 90112
//   tail overlay: y1 [0, 51200) = 128 rows * 100 f ; weights at 51200
// ============================================================================
#define A_STAGE 20480
#define SM_B0   40960
#define B_STAGE 24576
#define SM_W    51200
#define SMEM_BYTES 101504
// weight region float offsets (from sm + SM_W)
#define OW2E 0
#define OW2S 4608
#define OW3E 9216
#define OW3S 10368
#define OW4E 11520
#define OW4S 11808
#define OW5  12096
#define OE5  12120
#define OSE  12132
#define OT0  12196
#define OT1  12260

__global__ __launch_bounds__(256, 2) void fused_mma(
    const float* __restrict__ in,
    const float* __restrict__ sW2, const float* __restrict__ sW3,
    const float* __restrict__ sW4, const float* __restrict__ sW5,
    const float* __restrict__ eW2, const float* __restrict__ eW3,
    const float* __restrict__ eW4, const float* __restrict__ eW5,
    const float* __restrict__ s_seq, const float* __restrict__ s_pair,
    const float* __restrict__ e_seq, const float* __restrict__ e_pair,
    const float* __restrict__ cross_w,
    float* __restrict__ out)
{
    extern __shared__ __align__(1024) char sm[];
    float* y1f = (float*)sm;
    float* wf  = (float*)(sm + SM_W);

    const int tid = threadIdx.x;
    const int r0g = blockIdx.x * 32;

    const float ep0 = e_pair[0], ep1 = e_pair[1];
    const float sp0 = s_pair[0], sp1 = s_pair[1];
    const float es0 = e_seq[0], es1 = e_seq[1], es2 = e_seq[2], es3 = e_seq[3];
    const float ss0 = s_seq[0], ss1 = s_seq[1], ss2 = s_seq[2], ss3 = s_seq[3];

    // ---- builder mapping: 32 rows across 256 threads ----
    const int rb = tid >> 3;           // 0..31 batch row
    const int sk = tid & 7;            // float4 group within 32-k chunk
    const float* inp0 = in + (size_t)(r0g + rb) * 3072 + sk * 4;

    // ---- mma mapping: 8 warps, warp = m32 x n48 ----
    const int lane = tid & 31;
    const int w    = tid >> 5;          // 0..7
    const int br   = w >> 2;            // 0=e (w 0-3), 1=s (w 4-7)
    const int wm   = (w >> 1) & 1;      // m32 group within branch
    const int nh   = w & 1;             // n half
    const int fr   = lane >> 2;
    const int ql   = lane & 3;
    const int mb0  = br * 4 + wm * 2;   // first m16 block (0..7)

    // ldmatrix lane addressing (canonical m16k16 x4)
    const u32 lrow = (u32)((lane & 7) | (((lane >> 3) & 1) << 3));   // 0..15
    const u32 lkb  = (u32)((lane >> 4) * 16);                        // 0 or 16 B

    u64t gprep;
    asm("cvta.to.global.u64 %0, %1;" : "=l"(gprep) : "l"((const void*)g_prep));
    const u32 smbase = smem_u32(sm);
    const u32 b_sm = smbase + SM_B0;

    float acc[2][6][4];
#pragma unroll
    for (int im = 0; im < 2; im++)
#pragma unroll
        for (int nf = 0; nf < 6; nf++)
#pragma unroll
            for (int c = 0; c < 4; c++) acc[im][nf][c] = 0.f;

    float4 sA0, sA1, sA2, sA3;

#define LOAD_STAGE(kcv) { \
    const float* p0 = inp0 + (kcv) * 32; \
    sA0 = *(const float4*)p0; sA1 = *(const float4*)(p0 + 768); \
    sA2 = *(const float4*)(p0 + 1536); sA3 = *(const float4*)(p0 + 2304); }

#define BUILD_STAGE(stage) { \
    u32 off = (u32)(stage) * A_STAGE + (u32)rb * 160 + (u32)sk * 8; \
    float4 q; u64t hv, lv; \
    q.x = fmaxf(ep0*sA0.x + ep1*sA2.x, 0.f); q.y = fmaxf(ep0*sA0.y + ep1*sA2.y, 0.f); \
    q.z = fmaxf(ep0*sA0.z + ep1*sA2.z, 0.f); q.w = fmaxf(ep0*sA0.w + ep1*sA2.w, 0.f); \
    split4(q, hv, lv); \
    *(u64t*)(sm + off) = hv; *(u64t*)(sm + off + 10240) = lv; \
    q.x = fmaxf(es0*sA0.x + es1*sA1.x + es2*sA2.x + es3*sA3.x, 0.f); \
    q.y = fmaxf(es0*sA0.y + es1*sA1.y + es2*sA2.y + es3*sA3.y, 0.f); \
    q.z = fmaxf(es0*sA0.z + es1*sA1.z + es2*sA2.z + es3*sA3.z, 0.f); \
    q.w = fmaxf(es0*sA0.w + es1*sA1.w + es2*sA2.w + es3*sA3.w, 0.f); \
    split4(q, hv, lv); \
    *(u64t*)(sm + off + 80) = hv; *(u64t*)(sm + off + 80 + 10240) = lv; \
    q.x = fmaxf(sp0*sA0.x + sp1*sA2.x, 0.f); q.y = fmaxf(sp0*sA0.y + sp1*sA2.y, 0.f); \
    q.z = fmaxf(sp0*sA0.z + sp1*sA2.z, 0.f); q.w = fmaxf(sp0*sA0.w + sp1*sA2.w, 0.f); \
    split4(q, hv, lv); \
    *(u64t*)(sm + off + 5120) = hv; *(u64t*)(sm + off + 5120 + 10240) = lv; \
    q.x = fmaxf(ss0*sA0.x + ss1*sA1.x + ss2*sA2.x + ss3*sA3.x, 0.f); \
    q.y = fmaxf(ss0*sA0.y + ss1*sA1.y + ss2*sA2.y + ss3*sA3.y, 0.f); \
    q.z = fmaxf(ss0*sA0.z + ss1*sA1.z + ss2*sA2.z + ss3*sA3.z, 0.f); \
    q.w = fmaxf(ss0*sA0.w + ss1*sA1.w + ss2*sA2.w + ss3*sA3.w, 0.f); \
    split4(q, hv, lv); \
    *(u64t*)(sm + off + 5200) = hv; *(u64t*)(sm + off + 5200 + 10240) = lv; }

#define CPASYNC_B(stage, kcv) { \
    u64t gs = gprep + (u64t)(kcv) * 24576; \
    u32 db = b_sm + (u32)(stage) * B_STAGE; \
    _Pragma("unroll") \
    for (int j = 0; j < 6; j++) { \
        u32 i = (u32)tid * 16 + (u32)j * 4096; \
        asm volatile("cp.async.cg.shared.global [%0], [%1], 16;" \
                     :: "r"(db + i), "l"(gs + i) : "memory"); \
    } \
    asm volatile("cp.async.commit_group;" ::: "memory"); }

// one k16 step of MMAs for both m-blocks, all 6 nf, 3 passes
#define MMA_KS(ks) { \
    u32 aB = smbase + (u32)cur * A_STAGE + (u32)(mb0 * 16 + lrow) * 80 + lkb + (u32)(ks) * 32; \
    u32 ah0[4], ah1[4], al0[4], al1[4]; \
    LDSM_X4(ah0[0], ah0[1], ah0[2], ah0[3], aB); \
    LDSM_X4(ah1[0], ah1[1], ah1[2], ah1[3], aB + 1280); \
    LDSM_X4(al0[0], al0[1], al0[2], al0[3], aB + 10240); \
    LDSM_X4(al1[0], al1[1], al1[2], al1[3], aB + 11520); \
    u32 bsw = bbase + (u32)(((ks) ^ (fr & 1)) << 6); \
    _Pragma("unroll") \
    for (int nf = 0; nf < 6; nf++) { \
        uint4 bv = *(const uint4*)(sm + (bsw - smbase) + nf * 1024); \
        mma_bf16(acc[0][nf], ah0[0], ah0[1], ah0[2], ah0[3], bv.x, bv.y); \
        mma_bf16(acc[0][nf], al0[0], al0[1], al0[2], al0[3], bv.x, bv.y); \
        mma_bf16(acc[0][nf], ah0[0], ah0[1], ah0[2], ah0[3], bv.z, bv.w); \
        mma_bf16(acc[1][nf], ah1[0], ah1[1], ah1[2], ah1[3], bv.x, bv.y); \
        mma_bf16(acc[1][nf], al1[0], al1[1], al1[2], al1[3], bv.x, bv.y); \
        mma_bf16(acc[1][nf], ah1[0], ah1[1], ah1[2], ah1[3], bv.z, bv.w); \
    } }

    // ---- prologue ----
    LOAD_STAGE(0);
    BUILD_STAGE(0);
    CPASYNC_B(0, 0);
    LOAD_STAGE(1);
    asm volatile("cp.async.wait_group 0;" ::: "memory");
    __syncthreads();

    // ---- mainloop (branchless body) ----
    for (int kc = 0; kc < 24; kc++) {
        const int cur = kc & 1, nxt = cur ^ 1;
        const int kn = (kc < 23) ? kc + 1 : 23;
        const int kl = (kc < 22) ? kc + 2 : 23;
        const u32 bbase = b_sm + (u32)cur * B_STAGE + (u32)(br * 12288 + nh * 6144)
                        + (u32)fr * 128 + (u32)ql * 16;

        CPASYNC_B(nxt, kn);        // B for next chunk: latency hides under body
        MMA_KS(0);
        BUILD_STAGE(nxt);          // A for next chunk (from prefetched regs)
        MMA_KS(1);
        LOAD_STAGE(kl);            // LDG prefetch for chunk kc+2
        asm volatile("cp.async.wait_group 0;" ::: "memory");
        __syncthreads();
    }

    // ---- epilogue: relu(y1) -> [128][100] (overlays dead stage smem) ----
#pragma unroll
    for (int im = 0; im < 2; im++) {
        int m0 = (mb0 + im) * 16 + fr;
        int m1 = m0 + 8;
#pragma unroll
        for (int nf = 0; nf < 6; nf++) {
            int nb = (nh * 6 + nf) * 8 + ql * 2;
            *(u64t*)(y1f + m0 * 100 + nb) = pack2(fmaxf(acc[im][nf][0], 0.f), fmaxf(acc[im][nf][1], 0.f));
            *(u64t*)(y1f + m1 * 100 + nb) = pack2(fmaxf(acc[im][nf][2], 0.f), fmaxf(acc[im][nf][3], 0.f));
        }
    }
    // tail weights into overlay region (disjoint from y1)
    for (int i = tid; i < 4608; i += 256) { wf[OW2E + i] = eW2[i]; wf[OW2S + i] = sW2[i]; }
    for (int i = tid; i < 1152; i += 256) { wf[OW3E + i] = eW3[i]; wf[OW3S + i] = sW3[i]; }
    if (tid < 144) { wf[OW4E + tid] = eW4[tid]; wf[OW4E + 144 + tid] = eW4[144 + tid];
                     wf[OW4S + tid] = sW4[tid]; wf[OW4S + 144 + tid] = sW4[144 + tid]; }
    if (tid >= 160 && tid < 184) wf[OW5 + tid - 160] = sW5[tid - 160];
    if (tid >= 192 && tid < 204) {
        int k = tid - 192; float s = 0.f;
#pragma unroll
        for (int h = 0; h < 8; h++) s += eW5[h * 12 + k];
        wf[OE5 + k] = s;
    }
    __syncthreads();

    // ---- tail: 2 threads per vector, k-split + shfl combine ----
    {
        const int m  = tid >> 1;           // 0..127 vec row
        const int kh = tid & 1;            // k half
        const bool is_e = m < 64;
        const int r  = (m & 63) >> 1;
        const int vp = m & 1;

        u64t x[24];
        const u64t* xr = (const u64t*)(y1f + m * 100 + kh * 48);
#pragma unroll
        for (int i = 0; i < 24; i++) x[i] = xr[i];

        const float* W2 = wf + (is_e ? OW2E : OW2S) + kh * 48;
        float y2r[48];
#pragma unroll 4
        for (int n = 0; n < 48; n++) {
            const u64t* wr = (const u64t*)(W2 + n * 96);
            u64t s0 = 0, s1 = 0;
#pragma unroll
            for (int kp = 0; kp < 24; kp += 2) {
                s0 = fma2(x[kp], wr[kp], s0);
                s1 = fma2(x[kp + 1], wr[kp + 1], s1);
            }
            float s = red2(s0) + red2(s1);
            s += __shfl_xor_sync(0xffffffffu, s, 1);
            y2r[n] = fmaxf(s, 0.f);
        }

        u64t b2[12];
#pragma unroll
        for (int j = 0; j < 12; j++) b2[j] = pack2(y2r[kh * 24 + 2 * j], y2r[kh * 24 + 2 * j + 1]);
        const float* W3 = wf + (is_e ? OW3E : OW3S) + kh * 24;
        float y3r[24];
#pragma unroll
        for (int n = 0; n < 24; n++) {
            const u64t* wr = (const u64t*)(W3 + n * 48);
            u64t s0 = 0;
#pragma unroll
            for (int kp = 0; kp < 12; kp++) s0 = fma2(b2[kp], wr[kp], s0);
            float s = red2(s0);
            s += __shfl_xor_sync(0xffffffffu, s, 1);
            y3r[n] = fmaxf(s, 0.f);
        }

        u64t b3[6];
#pragma unroll
        for (int j = 0; j < 6; j++) b3[j] = pack2(y3r[kh * 12 + 2 * j], y3r[kh * 12 + 2 * j + 1]);
        const float* W4 = wf + (is_e ? OW4E : OW4S) + kh * 12;
        float r4[12];
#pragma unroll
        for (int n = 0; n < 12; n++) {
            const u64t* wr = (const u64t*)(W4 + n * 24);
            u64t s0 = 0;
#pragma unroll
            for (int kp = 0; kp < 6; kp++) s0 = fma2(b3[kp], wr[kp], s0);
            float s = red2(s0);
            s += __shfl_xor_sync(0xffffffffu, s, 1);
            r4[n] = fmaxf(s, 0.f);       // relu before W5
        }

        if (kh == 0) {
            const int idx2 = r * 2 + vp;
            if (is_e) {
                float Se = 0.f;
#pragma unroll
                for (int k = 0; k < 12; k++) Se = fmaf(r4[k], wf[OE5 + k], Se);
                wf[OSE + idx2] = Se;
            } else {
                float t0 = 0.f, t1 = 0.f;
#pragma unroll
                for (int k = 0; k < 12; k++) {
                    t0 = fmaf(r4[k], wf[OW5 + k], t0);
                    t1 = fmaf(r4[k], wf[OW5 + 12 + k], t1);
                }
                wf[OT0 + idx2] = t0;
                wf[OT1 + idx2] = t1;
            }
        }
    }
    __syncthreads();

    if (tid < 32) {
        const int r = tid;
        const float cw0 = cross_w[0], cw1 = cross_w[1];
        float SeP = wf[OSE + 2*r], SeS = wf[OSE + 2*r + 1];
        float o0 = cw0 * SeP * wf[OT0 + 2*r] + cw1 * SeS * wf[OT0 + 2*r + 1];
        float o1 = cw0 * SeP * wf[OT1 + 2*r] + cw1 * SeS * wf[OT1 + 2*r + 1];
        out[(size_t)(r0g + r) * 2 + 0] = o0;
        out[(size_t)(r0g + r) * 2 + 1] = o1;
    }
}

// ============================================================================
extern "C" void kernel_launch(void* const* d_in, const int* in_sizes, int n_in,
                              void* d_out, int out_size)
{
    const float* in      = (const float*)d_in[0];
    const float* sW1     = (const float*)d_in[1];
    const float* sW2     = (const float*)d_in[2];
    const float* sW3     = (const float*)d_in[3];
    const float* sW4     = (const float*)d_in[4];
    const float* sW5     = (const float*)d_in[5];
    const float* eW1     = (const float*)d_in[6];
    const float* eW2     = (const float*)d_in[7];
    const float* eW3     = (const float*)d_in[8];
    const float* eW4     = (const float*)d_in[9];
    const float* eW5     = (const float*)d_in[10];
    const float* s_seq   = (const float*)d_in[11];
    const float* s_pair  = (const float*)d_in[12];
    const float* e_seq   = (const float*)d_in[13];
    const float* e_pair  = (const float*)d_in[14];
    const float* cross_w = (const float*)d_in[15];
    float* out = (float*)d_out;

    const int B = in_sizes[0] / 3072;   // 65536

    static int init_done = 0;
    if (!init_done) {
        cudaFuncSetAttribute(fused_mma, cudaFuncAttributeMaxDynamicSharedMemorySize, SMEM_BYTES);
        init_done = 1;
    }
    prep_w1<<<144, 256>>>(eW1, sW1);
    fused_mma<<<B / 32, 256, SMEM_BYTES>>>(
        in, sW2, sW3, sW4, sW5, eW2, eW3, eW4, eW5,
        s_seq, s_pair, e_seq, e_pair, cross_w, out);
}

// round 12
// speedup vs baseline: 1.4517x; 1.1531x over previous
#include <cuda_runtime.h>
#include <cuda_fp16.h>
#include <cstdint>

typedef unsigned int u32;
typedef unsigned long long u64t;

// ============================================================================
// g_prep: packed, fragment-ordered fp16 W1 (single precision weights).
// [kc 0..23][br 0..1][n 0..95][q 0..3] -> 16B uint4:
//   {ks0:(w[2q],w[2q+1]), ks0:(w[8+2q],w[8+2q+1]),
//    ks1:(w[16+2q],w[16+2q+1]), ks1:(w[24+2q],w[24+2q+1])}   (k base = kc*32)
// ============================================================================
__device__ __align__(16) u32 g_prep[24 * 2 * 96 * 16];   // 294912 B

__device__ __forceinline__ u32 pack_half(float a, float b) {
    __half2 h = __floats2half2_rn(a, b);
    return *(u32*)&h;
}

__global__ void prep_w1(const float* __restrict__ eW1, const float* __restrict__ sW1)
{
    int idx = blockIdx.x * 256 + threadIdx.x;        // 0 .. 18431
    if (idx >= 18432) return;
    int q  = idx & 3;
    int n  = (idx >> 2) % 96;
    int t  = (idx >> 2) / 96;
    int kc = t % 24;
    int br = t / 24;
    const float* W = (br ? sW1 : eW1) + (size_t)n * 768 + kc * 32;
    uint4 v;
    v.x = pack_half(W[2*q],      W[2*q+1]);
    v.y = pack_half(W[8+2*q],    W[8+2*q+1]);
    v.z = pack_half(W[16+2*q],   W[16+2*q+1]);
    v.w = pack_half(W[24+2*q],   W[24+2*q+1]);
    u32 off = (u32)kc * 12288 + (u32)br * 6144 + (u32)n * 64 + (u32)q * 16;
    *(uint4*)((char*)g_prep + off) = v;
}

// ============================================================================
// helpers
// ============================================================================
__device__ __forceinline__ u32 smem_u32(const void* p) {
    u32 a;
    asm("{ .reg .u64 t; cvta.to.shared.u64 t, %1; cvt.u32.u64 %0, t; }" : "=r"(a) : "l"(p));
    return a;
}
__device__ __forceinline__ u64t fma2(u64t a, u64t b, u64t c) {
    u64t d;
    asm("fma.rn.f32x2 %0, %1, %2, %3;" : "=l"(d) : "l"(a), "l"(b), "l"(c));
    return d;
}
__device__ __forceinline__ float red2(u64t v) {
    return __uint_as_float((u32)v) + __uint_as_float((u32)(v >> 32));
}
__device__ __forceinline__ u64t pack2(float lo, float hi) {
    return (u64t)__float_as_uint(lo) | ((u64t)__float_as_uint(hi) << 32);
}
// fp16 hi/lo split of 4 floats
__device__ __forceinline__ void split4(float4 q, u64t& hv, u64t& lv) {
    __half2 h01 = __floats2half2_rn(q.x, q.y);
    __half2 h23 = __floats2half2_rn(q.z, q.w);
    float2 f01 = __half22float2(h01);
    float2 f23 = __half22float2(h23);
    __half2 l01 = __floats2half2_rn(q.x - f01.x, q.y - f01.y);
    __half2 l23 = __floats2half2_rn(q.z - f23.x, q.w - f23.y);
    hv = (u64t)(*(u32*)&h01) | ((u64t)(*(u32*)&h23) << 32);
    lv = (u64t)(*(u32*)&l01) | ((u64t)(*(u32*)&l23) << 32);
}
__device__ __forceinline__ void mma_f16(float c[4], u32 a0, u32 a1, u32 a2, u32 a3,
                                        u32 b0, u32 b1) {
    asm volatile("mma.sync.aligned.m16n8k16.row.col.f32.f16.f16.f32 "
        "{%0,%1,%2,%3}, {%4,%5,%6,%7}, {%8,%9}, {%0,%1,%2,%3};"
        : "+f"(c[0]), "+f"(c[1]), "+f"(c[2]), "+f"(c[3])
        : "r"(a0), "r"(a1), "r"(a2), "r"(a3), "r"(b0), "r"(b1));
}
#define LDSM_X4(d0, d1, d2, d3, a) \
    asm volatile("ldmatrix.sync.aligned.m8n8.x4.shared.b16 {%0,%1,%2,%3}, [%4];" \
        : "=r"(d0), "=r"(d1), "=r"(d2), "=r"(d3) : "r"(a))

// ============================================================================
// smem layout (bytes), per 256-thread CTA (2 CTAs/SM)
//   A stages: stage*20480; hi at +0 (128 vec rows * 80B), lo at +10240
//   B stages: 40960 + stage*12288  -> ends 65536
//   tail overlay: y1 [0, 51200) = 128 rows * 100 f ; weights at 51200
// ============================================================================
#define A_STAGE 20480
#define SM_B0   40960
#define B_STAGE 12288
#define SM_W    51200
#define SMEM_BYTES 101504
// weight region float offsets (from sm + SM_W)
#define OW2E 0
#define OW2S 4608
#define OW3E 9216
#define OW3S 10368
#define OW4E 11520
#define OW4S 11808
#define OW5  12096
#define OE5  12120
#define OSE  12132
#define OT0  12196
#define OT1  12260

__global__ __launch_bounds__(256, 2) void fused_mma(
    const float* __restrict__ in,
    const float* __restrict__ sW2, const float* __restrict__ sW3,
    const float* __restrict__ sW4, const float* __restrict__ sW5,
    const float* __restrict__ eW2, const float* __restrict__ eW3,
    const float* __restrict__ eW4, const float* __restrict__ eW5,
    const float* __restrict__ s_seq, const float* __restrict__ s_pair,
    const float* __restrict__ e_seq, const float* __restrict__ e_pair,
    const float* __restrict__ cross_w,
    float* __restrict__ out)
{
    extern __shared__ __align__(1024) char sm[];
    float* y1f = (float*)sm;
    float* wf  = (float*)(sm + SM_W);

    const int tid = threadIdx.x;
    const int r0g = blockIdx.x * 32;

    const float ep0 = e_pair[0], ep1 = e_pair[1];
    const float sp0 = s_pair[0], sp1 = s_pair[1];
    const float es0 = e_seq[0], es1 = e_seq[1], es2 = e_seq[2], es3 = e_seq[3];
    const float ss0 = s_seq[0], ss1 = s_seq[1], ss2 = s_seq[2], ss3 = s_seq[3];

    // ---- builder mapping: 32 rows across 256 threads ----
    const int rb = tid >> 3;           // 0..31 batch row
    const int sk = tid & 7;            // float4 group within 32-k chunk
    const float* inp0 = in + (size_t)(r0g + rb) * 3072 + sk * 4;

    // ---- mma mapping: 8 warps, warp = m32 x n48 ----
    const int lane = tid & 31;
    const int w    = tid >> 5;          // 0..7
    const int br   = w >> 2;            // 0=e, 1=s
    const int wm   = (w >> 1) & 1;      // m32 group within branch
    const int nh   = w & 1;             // n half
    const int fr   = lane >> 2;
    const int ql   = lane & 3;
    const int mb0  = br * 4 + wm * 2;   // first m16 block (0..7)

    // ldmatrix lane addressing (canonical m16k16 x4)
    const u32 lrow = (u32)((lane & 7) | (((lane >> 3) & 1) << 3));   // 0..15
    const u32 lkb  = (u32)((lane >> 4) * 16);                        // 0 or 16 B

    u64t gprep;
    asm("cvta.to.global.u64 %0, %1;" : "=l"(gprep) : "l"((const void*)g_prep));
    const u32 smbase = smem_u32(sm);
    const u32 b_sm = smbase + SM_B0;

    float acc[2][6][4];
#pragma unroll
    for (int im = 0; im < 2; im++)
#pragma unroll
        for (int nf = 0; nf < 6; nf++)
#pragma unroll
            for (int c = 0; c < 4; c++) acc[im][nf][c] = 0.f;

    float4 sA0, sA1, sA2, sA3;

#define LOAD_STAGE(kcv) { \
    const float* p0 = inp0 + (kcv) * 32; \
    sA0 = *(const float4*)p0; sA1 = *(const float4*)(p0 + 768); \
    sA2 = *(const float4*)(p0 + 1536); sA3 = *(const float4*)(p0 + 2304); }

#define BUILD_STAGE(stage) { \
    u32 off = (u32)(stage) * A_STAGE + (u32)rb * 160 + (u32)sk * 8; \
    float4 q; u64t hv, lv; \
    q.x = fmaxf(ep0*sA0.x + ep1*sA2.x, 0.f); q.y = fmaxf(ep0*sA0.y + ep1*sA2.y, 0.f); \
    q.z = fmaxf(ep0*sA0.z + ep1*sA2.z, 0.f); q.w = fmaxf(ep0*sA0.w + ep1*sA2.w, 0.f); \
    split4(q, hv, lv); \
    *(u64t*)(sm + off) = hv; *(u64t*)(sm + off + 10240) = lv; \
    q.x = fmaxf(es0*sA0.x + es1*sA1.x + es2*sA2.x + es3*sA3.x, 0.f); \
    q.y = fmaxf(es0*sA0.y + es1*sA1.y + es2*sA2.y + es3*sA3.y, 0.f); \
    q.z = fmaxf(es0*sA0.z + es1*sA1.z + es2*sA2.z + es3*sA3.z, 0.f); \
    q.w = fmaxf(es0*sA0.w + es1*sA1.w + es2*sA2.w + es3*sA3.w, 0.f); \
    split4(q, hv, lv); \
    *(u64t*)(sm + off + 80) = hv; *(u64t*)(sm + off + 80 + 10240) = lv; \
    q.x = fmaxf(sp0*sA0.x + sp1*sA2.x, 0.f); q.y = fmaxf(sp0*sA0.y + sp1*sA2.y, 0.f); \
    q.z = fmaxf(sp0*sA0.z + sp1*sA2.z, 0.f); q.w = fmaxf(sp0*sA0.w + sp1*sA2.w, 0.f); \
    split4(q, hv, lv); \
    *(u64t*)(sm + off + 5120) = hv; *(u64t*)(sm + off + 5120 + 10240) = lv; \
    q.x = fmaxf(ss0*sA0.x + ss1*sA1.x + ss2*sA2.x + ss3*sA3.x, 0.f); \
    q.y = fmaxf(ss0*sA0.y + ss1*sA1.y + ss2*sA2.y + ss3*sA3.y, 0.f); \
    q.z = fmaxf(ss0*sA0.z + ss1*sA1.z + ss2*sA2.z + ss3*sA3.z, 0.f); \
    q.w = fmaxf(ss0*sA0.w + ss1*sA1.w + ss2*sA2.w + ss3*sA3.w, 0.f); \
    split4(q, hv, lv); \
    *(u64t*)(sm + off + 5200) = hv; *(u64t*)(sm + off + 5200 + 10240) = lv; }

#define CPASYNC_B(stage, kcv) { \
    u64t gs = gprep + (u64t)(kcv) * 12288; \
    u32 db = b_sm + (u32)(stage) * B_STAGE; \
    _Pragma("unroll") \
    for (int j = 0; j < 3; j++) { \
        u32 i = (u32)tid * 16 + (u32)j * 4096; \
        asm volatile("cp.async.cg.shared.global [%0], [%1], 16;" \
                     :: "r"(db + i), "l"(gs + i) : "memory"); \
    } \
    asm volatile("cp.async.commit_group;" ::: "memory"); }

    // ---- prologue ----
    LOAD_STAGE(0);
    BUILD_STAGE(0);
    CPASYNC_B(0, 0);
    LOAD_STAGE(1);
    asm volatile("cp.async.wait_group 0;" ::: "memory");
    __syncthreads();

    // ---- mainloop (branchless body) ----
    for (int kc = 0; kc < 24; kc++) {
        const int cur = kc & 1, nxt = cur ^ 1;
        const int kn = (kc < 23) ? kc + 1 : 23;
        const int kl = (kc < 22) ? kc + 2 : 23;
        const u32 bbase = b_sm + (u32)cur * B_STAGE + (u32)(br * 6144 + nh * 3072)
                        + (u32)fr * 64 + (u32)ql * 16;

        CPASYNC_B(nxt, kn);        // B for next chunk: latency hides under body

        // load all B fragments for this chunk (both k16 steps packed per uint4)
        uint4 bv[6];
#pragma unroll
        for (int nf = 0; nf < 6; nf++)
            bv[nf] = *(const uint4*)(sm + (bbase - smbase) + nf * 512);

        // k16 step 0 (B frags bv.x, bv.y)
        {
            u32 aB = smbase + (u32)cur * A_STAGE + (u32)(mb0 * 16 + lrow) * 80 + lkb;
            u32 ah0[4], ah1[4], al0[4], al1[4];
            LDSM_X4(ah0[0], ah0[1], ah0[2], ah0[3], aB);
            LDSM_X4(ah1[0], ah1[1], ah1[2], ah1[3], aB + 1280);
            LDSM_X4(al0[0], al0[1], al0[2], al0[3], aB + 10240);
            LDSM_X4(al1[0], al1[1], al1[2], al1[3], aB + 11520);
#pragma unroll
            for (int nf = 0; nf < 6; nf++) {
                mma_f16(acc[0][nf], ah0[0], ah0[1], ah0[2], ah0[3], bv[nf].x, bv[nf].y);
                mma_f16(acc[0][nf], al0[0], al0[1], al0[2], al0[3], bv[nf].x, bv[nf].y);
                mma_f16(acc[1][nf], ah1[0], ah1[1], ah1[2], ah1[3], bv[nf].x, bv[nf].y);
                mma_f16(acc[1][nf], al1[0], al1[1], al1[2], al1[3], bv[nf].x, bv[nf].y);
            }
        }
        BUILD_STAGE(nxt);          // A for next chunk (from prefetched regs)
        // k16 step 1 (B frags bv.z, bv.w)
        {
            u32 aB = smbase + (u32)cur * A_STAGE + (u32)(mb0 * 16 + lrow) * 80 + lkb + 32;
            u32 ah0[4], ah1[4], al0[4], al1[4];
            LDSM_X4(ah0[0], ah0[1], ah0[2], ah0[3], aB);
            LDSM_X4(ah1[0], ah1[1], ah1[2], ah1[3], aB + 1280);
            LDSM_X4(al0[0], al0[1], al0[2], al0[3], aB + 10240);
            LDSM_X4(al1[0], al1[1], al1[2], al1[3], aB + 11520);
#pragma unroll
            for (int nf = 0; nf < 6; nf++) {
                mma_f16(acc[0][nf], ah0[0], ah0[1], ah0[2], ah0[3], bv[nf].z, bv[nf].w);
                mma_f16(acc[0][nf], al0[0], al0[1], al0[2], al0[3], bv[nf].z, bv[nf].w);
                mma_f16(acc[1][nf], ah1[0], ah1[1], ah1[2], ah1[3], bv[nf].z, bv[nf].w);
                mma_f16(acc[1][nf], al1[0], al1[1], al1[2], al1[3], bv[nf].z, bv[nf].w);
            }
        }
        LOAD_STAGE(kl);            // LDG prefetch for chunk kc+2
        asm volatile("cp.async.wait_group 0;" ::: "memory");
        __syncthreads();
    }

    // ---- epilogue: relu(y1) -> [128][100] (overlays dead stage smem) ----
#pragma unroll
    for (int im = 0; im < 2; im++) {
        int m0 = (mb0 + im) * 16 + fr;
        int m1 = m0 + 8;
#pragma unroll
        for (int nf = 0; nf < 6; nf++) {
            int nb = (nh * 6 + nf) * 8 + ql * 2;
            *(u64t*)(y1f + m0 * 100 + nb) = pack2(fmaxf(acc[im][nf][0], 0.f), fmaxf(acc[im][nf][1], 0.f));
            *(u64t*)(y1f + m1 * 100 + nb) = pack2(fmaxf(acc[im][nf][2], 0.f), fmaxf(acc[im][nf][3], 0.f));
        }
    }
    // tail weights into overlay region (disjoint from y1)
    for (int i = tid; i < 4608; i += 256) { wf[OW2E + i] = eW2[i]; wf[OW2S + i] = sW2[i]; }
    for (int i = tid; i < 1152; i += 256) { wf[OW3E + i] = eW3[i]; wf[OW3S + i] = sW3[i]; }
    if (tid < 144) { wf[OW4E + tid] = eW4[tid]; wf[OW4E + 144 + tid] = eW4[144 + tid];
                     wf[OW4S + tid] = sW4[tid]; wf[OW4S + 144 + tid] = sW4[144 + tid]; }
    if (tid >= 160 && tid < 184) wf[OW5 + tid - 160] = sW5[tid - 160];
    if (tid >= 192 && tid < 204) {
        int k = tid - 192; float s = 0.f;
#pragma unroll
        for (int h = 0; h < 8; h++) s += eW5[h * 12 + k];
        wf[OE5 + k] = s;
    }
    __syncthreads();

    // ---- tail: 2 threads per vector, k-split + shfl combine ----
    {
        const int m  = tid >> 1;           // 0..127 vec row
        const int kh = tid & 1;            // k half
        const bool is_e = m < 64;
        const int r  = (m & 63) >> 1;
        const int vp = m & 1;

        u64t x[24];
        const u64t* xr = (const u64t*)(y1f + m * 100 + kh * 48);
#pragma unroll
        for (int i = 0; i < 24; i++) x[i] = xr[i];

        const float* W2 = wf + (is_e ? OW2E : OW2S) + kh * 48;
        float y2r[48];
#pragma unroll 4
        for (int n = 0; n < 48; n++) {
            const u64t* wr = (const u64t*)(W2 + n * 96);
            u64t s0 = 0, s1 = 0;
#pragma unroll
            for (int kp = 0; kp < 24; kp += 2) {
                s0 = fma2(x[kp], wr[kp], s0);
                s1 = fma2(x[kp + 1], wr[kp + 1], s1);
            }
            float s = red2(s0) + red2(s1);
            s += __shfl_xor_sync(0xffffffffu, s, 1);
            y2r[n] = fmaxf(s, 0.f);
        }

        u64t b2[12];
#pragma unroll
        for (int j = 0; j < 12; j++) b2[j] = pack2(y2r[kh * 24 + 2 * j], y2r[kh * 24 + 2 * j + 1]);
        const float* W3 = wf + (is_e ? OW3E : OW3S) + kh * 24;
        float y3r[24];
#pragma unroll
        for (int n = 0; n < 24; n++) {
            const u64t* wr = (const u64t*)(W3 + n * 48);
            u64t s0 = 0;
#pragma unroll
            for (int kp = 0; kp < 12; kp++) s0 = fma2(b2[kp], wr[kp], s0);
            float s = red2(s0);
            s += __shfl_xor_sync(0xffffffffu, s, 1);
            y3r[n] = fmaxf(s, 0.f);
        }

        u64t b3[6];
#pragma unroll
        for (int j = 0; j < 6; j++) b3[j] = pack2(y3r[kh * 12 + 2 * j], y3r[kh * 12 + 2 * j + 1]);
        const float* W4 = wf + (is_e ? OW4E : OW4S) + kh * 12;
        float r4[12];
#pragma unroll
        for (int n = 0; n < 12; n++) {
            const u64t* wr = (const u64t*)(W4 + n * 24);
            u64t s0 = 0;
#pragma unroll
            for (int kp = 0; kp < 6; kp++) s0 = fma2(b3[kp], wr[kp], s0);
            float s = red2(s0);
            s += __shfl_xor_sync(0xffffffffu, s, 1);
            r4[n] = fmaxf(s, 0.f);       // relu before W5
        }

        if (kh == 0) {
            const int idx2 = r * 2 + vp;
            if (is_e) {
                float Se = 0.f;
#pragma unroll
                for (int k = 0; k < 12; k++) Se = fmaf(r4[k], wf[OE5 + k], Se);
                wf[OSE + idx2] = Se;
            } else {
                float t0 = 0.f, t1 = 0.f;
#pragma unroll
                for (int k = 0; k < 12; k++) {
                    t0 = fmaf(r4[k], wf[OW5 + k], t0);
                    t1 = fmaf(r4[k], wf[OW5 + 12 + k], t1);
                }
                wf[OT0 + idx2] = t0;
                wf[OT1 + idx2] = t1;
            }
        }
    }
    __syncthreads();

    if (tid < 32) {
        const int r = tid;
        const float cw0 = cross_w[0], cw1 = cross_w[1];
        float SeP = wf[OSE + 2*r], SeS = wf[OSE + 2*r + 1];
        float o0 = cw0 * SeP * wf[OT0 + 2*r] + cw1 * SeS * wf[OT0 + 2*r + 1];
        float o1 = cw0 * SeP * wf[OT1 + 2*r] + cw1 * SeS * wf[OT1 + 2*r + 1];
        out[(size_t)(r0g + r) * 2 + 0] = o0;
        out[(size_t)(r0g + r) * 2 + 1] = o1;
    }
}

// ============================================================================
extern "C" void kernel_launch(void* const* d_in, const int* in_sizes, int n_in,
                              void* d_out, int out_size)
{
    const float* in      = (const float*)d_in[0];
    const float* sW1     = (const float*)d_in[1];
    const float* sW2     = (const float*)d_in[2];
    const float* sW3     = (const float*)d_in[3];
    const float* sW4     = (const float*)d_in[4];
    const float* sW5     = (const float*)d_in[5];
    const float* eW1     = (const float*)d_in[6];
    const float* eW2     = (const float*)d_in[7];
    const float* eW3     = (const float*)d_in[8];
    const float* eW4     = (const float*)d_in[9];
    const float* eW5     = (const float*)d_in[10];
    const float* s_seq   = (const float*)d_in[11];
    const float* s_pair  = (const float*)d_in[12];
    const float* e_seq   = (const float*)d_in[13];
    const float* e_pair  = (const float*)d_in[14];
    const float* cross_w = (const float*)d_in[15];
    float* out = (float*)d_out;

    const int B = in_sizes[0] / 3072;   // 65536

    static int init_done = 0;
    if (!init_done) {
        cudaFuncSetAttribute(fused_mma, cudaFuncAttributeMaxDynamicSharedMemorySize, SMEM_BYTES);
        init_done = 1;
    }
    prep_w1<<<72, 256>>>(eW1, sW1);
    fused_mma<<<B / 32, 256, SMEM_BYTES>>>(
        in, sW2, sW3, sW4, sW5, eW2, eW3, eW4, eW5,
        s_seq, s_pair, e_seq, e_pair, cross_w, out);
}